// round 3
// baseline (speedup 1.0000x reference)
#include <cuda_runtime.h>
#include <math.h>

#define NN 100000
#define EE 3200000
#define FF 13
#define HH 64
#define GG 512
#define POOLW 192
#define BN_EPS 1e-5f

// ---------------- scratch (device globals: allocation-free) ----------------
__device__ int   g_deg[NN];
__device__ int   g_rowptr[NN + 1];
__device__ int   g_cursor[NN];
__device__ int   g_col[EE];
__device__ float g_agg[NN * 64];
__device__ float g_hA[NN * 64];
__device__ float g_hB[NN * 64];
__device__ float g_pool[GG * POOLW];

// ---------------- CSR build ----------------
__global__ void init_zero_kernel() {
    int i = blockIdx.x * blockDim.x + threadIdx.x;
    if (i < NN) g_deg[i] = 0;
    if (i < GG * POOLW) g_pool[i] = 0.f;
}

__global__ void hist_kernel(const int* __restrict__ dst) {
    int i = blockIdx.x * blockDim.x + threadIdx.x;
    if (i < EE) atomicAdd(&g_deg[dst[i]], 1);
}

// Single-block looped exclusive scan over g_deg -> g_rowptr
__global__ void scan_kernel() {
    __shared__ int wsum[32];
    __shared__ int carry;
    int tid = threadIdx.x;
    if (tid == 0) carry = 0;
    __syncthreads();
    for (int base = 0; base < NN; base += 1024) {
        int i = base + tid;
        int v = (i < NN) ? g_deg[i] : 0;
        int x = v;
#pragma unroll
        for (int o = 1; o < 32; o <<= 1) {
            int y = __shfl_up_sync(0xffffffffu, x, o);
            if ((tid & 31) >= o) x += y;
        }
        if ((tid & 31) == 31) wsum[tid >> 5] = x;
        __syncthreads();
        if (tid < 32) {
            int s = wsum[tid];
            int xs = s;
#pragma unroll
            for (int o = 1; o < 32; o <<= 1) {
                int y = __shfl_up_sync(0xffffffffu, xs, o);
                if (tid >= o) xs += y;
            }
            wsum[tid] = xs - s;  // exclusive warp offsets
        }
        __syncthreads();
        int incl = x + wsum[tid >> 5] + carry;
        if (i < NN) g_rowptr[i] = incl - v;  // exclusive scan
        __syncthreads();
        if (tid == 1023) carry = incl;
        __syncthreads();
    }
    if (tid == 0) g_rowptr[NN] = carry;
}

__global__ void cursor_kernel() {
    int i = blockIdx.x * blockDim.x + threadIdx.x;
    if (i < NN) g_cursor[i] = g_rowptr[i];
}

__global__ void scatter_kernel(const int* __restrict__ src, const int* __restrict__ dst) {
    int i = blockIdx.x * blockDim.x + threadIdx.x;
    if (i < EE) {
        int p = atomicAdd(&g_cursor[dst[i]], 1);
        g_col[p] = src[i];
    }
}

// ---------------- aggregation: one warp per node, CSR gather-sum ----------------
template <int FIN>
__global__ void agg_kernel(const float* __restrict__ xin, float* __restrict__ out) {
    int gt = blockIdx.x * blockDim.x + threadIdx.x;
    int node = gt >> 5;
    int lane = gt & 31;
    if (node >= NN) return;
    constexpr int PER = (FIN + 31) / 32;
    float acc[PER];
#pragma unroll
    for (int p = 0; p < PER; p++) {
        int f = lane + 32 * p;
        acc[p] = (f < FIN) ? xin[node * FIN + f] : 0.f;  // self term (x + agg)
    }
    int s = g_rowptr[node];
    int e = g_rowptr[node + 1];
    for (int t = s; t < e; t++) {
        int j = g_col[t];
#pragma unroll
        for (int p = 0; p < PER; p++) {
            int f = lane + 32 * p;
            if (f < FIN) acc[p] += __ldg(&xin[j * FIN + f]);
        }
    }
#pragma unroll
    for (int p = 0; p < PER; p++) {
        int f = lane + 32 * p;
        if (f < FIN) out[node * FIN + f] = acc[p];
    }
}

// ---------------- fused MLP (Linear->BN->ReLU->Linear->ReLU) + pooling ----------------
// 64-node tile per block, 256 threads, 4x4 register micro-tiles, 48KB static smem.
template <int FIN>
__global__ void __launch_bounds__(256)
mlp_kernel(const float* __restrict__ agg,
           const float* __restrict__ W1, const float* __restrict__ b1,
           const float* __restrict__ gam, const float* __restrict__ bet,
           const float* __restrict__ mu, const float* __restrict__ var,
           const float* __restrict__ W2, const float* __restrict__ b2,
           const int* __restrict__ batch,
           float* __restrict__ hout, int pool_off) {
    __shared__ float As[64 * 64];   // A tile, later reused for T (hidden activations)
    __shared__ float W1s[64 * 64];
    __shared__ float W2s[64 * 64];
    int tid = threadIdx.x;
    int node0 = blockIdx.x * 64;

    for (int idx = tid; idx < FIN * 64; idx += 256) W1s[idx] = W1[idx];
    for (int idx = tid; idx < 64 * 64; idx += 256) W2s[idx] = W2[idx];
    for (int idx = tid; idx < 64 * FIN; idx += 256) {
        int r = idx / FIN;
        int c = idx - r * FIN;
        int node = node0 + r;
        As[r * 64 + c] = (node < NN) ? agg[node * FIN + c] : 0.f;
    }
    __syncthreads();

    int ty = tid >> 4, tx = tid & 15;
    int r0 = 4 * ty, c0 = 4 * tx;

    // GEMM1: T = A @ W1
    float acc[4][4];
#pragma unroll
    for (int i = 0; i < 4; i++)
#pragma unroll
        for (int j = 0; j < 4; j++) acc[i][j] = 0.f;

#pragma unroll 4
    for (int k = 0; k < FIN; k++) {
        float a[4], b[4];
#pragma unroll
        for (int i = 0; i < 4; i++) a[i] = As[(r0 + i) * 64 + k];
#pragma unroll
        for (int j = 0; j < 4; j++) b[j] = W1s[k * 64 + c0 + j];
#pragma unroll
        for (int i = 0; i < 4; i++)
#pragma unroll
            for (int j = 0; j < 4; j++) acc[i][j] = fmaf(a[i], b[j], acc[i][j]);
    }

    // +b1 -> BatchNorm (running stats) -> ReLU
    float t1[4][4];
#pragma unroll
    for (int j = 0; j < 4; j++) {
        int col = c0 + j;
        float s = gam[col] * rsqrtf(var[col] + BN_EPS);
        float bb = bet[col] - mu[col] * s;
        float bias = b1[col];
#pragma unroll
        for (int i = 0; i < 4; i++)
            t1[i][j] = fmaxf(fmaf(acc[i][j] + bias, s, bb), 0.f);
    }
    __syncthreads();  // all reads of As done
#pragma unroll
    for (int i = 0; i < 4; i++)
#pragma unroll
        for (int j = 0; j < 4; j++) As[(r0 + i) * 64 + c0 + j] = t1[i][j];
    __syncthreads();

    // GEMM2: O = T @ W2
    float acc2[4][4];
#pragma unroll
    for (int i = 0; i < 4; i++)
#pragma unroll
        for (int j = 0; j < 4; j++) acc2[i][j] = 0.f;

#pragma unroll 4
    for (int k = 0; k < 64; k++) {
        float a[4], b[4];
#pragma unroll
        for (int i = 0; i < 4; i++) a[i] = As[(r0 + i) * 64 + k];
#pragma unroll
        for (int j = 0; j < 4; j++) b[j] = W2s[k * 64 + c0 + j];
#pragma unroll
        for (int i = 0; i < 4; i++)
#pragma unroll
            for (int j = 0; j < 4; j++) acc2[i][j] = fmaf(a[i], b[j], acc2[i][j]);
    }

    // epilogue: +b2, ReLU, write h_out, fused graph pooling (atomic scatter)
#pragma unroll
    for (int i = 0; i < 4; i++) {
        int node = node0 + r0 + i;
        if (node < NN) {
            int gid = batch[node];
#pragma unroll
            for (int j = 0; j < 4; j++) {
                int col = c0 + j;
                float o = fmaxf(acc2[i][j] + b2[col], 0.f);
                hout[node * 64 + col] = o;
                atomicAdd(&g_pool[gid * POOLW + pool_off + col], o);
            }
        }
    }
}

// ---------------- head: fc1(192->192)+ReLU, fc2(192->2), log_softmax ----------------
__global__ void head_kernel(const float* __restrict__ fc1W, const float* __restrict__ fc1b,
                            const float* __restrict__ fc2W, const float* __restrict__ fc2b,
                            float* __restrict__ out) {
    __shared__ float h[POOLW];
    __shared__ float h2[POOLW];
    __shared__ float r0s[6], r1s[6];
    int g = blockIdx.x, t = threadIdx.x;
    h[t] = g_pool[g * POOLW + t];
    __syncthreads();
    float acc = fc1b[t];
#pragma unroll 8
    for (int k = 0; k < POOLW; k++) acc = fmaf(h[k], fc1W[k * POOLW + t], acc);
    h2[t] = fmaxf(acc, 0.f);
    __syncthreads();
    float p0 = h2[t] * fc2W[t * 2 + 0];
    float p1 = h2[t] * fc2W[t * 2 + 1];
#pragma unroll
    for (int o = 16; o > 0; o >>= 1) {
        p0 += __shfl_down_sync(0xffffffffu, p0, o);
        p1 += __shfl_down_sync(0xffffffffu, p1, o);
    }
    if ((t & 31) == 0) { r0s[t >> 5] = p0; r1s[t >> 5] = p1; }
    __syncthreads();
    if (t == 0) {
        float z0 = fc2b[0], z1 = fc2b[1];
#pragma unroll
        for (int w = 0; w < 6; w++) { z0 += r0s[w]; z1 += r1s[w]; }
        float mx = fmaxf(z0, z1);
        float lse = mx + logf(expf(z0 - mx) + expf(z1 - mx));
        out[g * 2 + 0] = z0 - lse;
        out[g * 2 + 1] = z1 - lse;
    }
}

// ---------------- launch ----------------
extern "C" void kernel_launch(void* const* d_in, const int* in_sizes, int n_in,
                              void* d_out, int out_size) {
    const float* x     = (const float*)d_in[0];
    const int*   src   = (const int*)d_in[1];
    const int*   dst   = (const int*)d_in[2];
    const int*   batch = (const int*)d_in[3];

    const float* c1p[8]; for (int i = 0; i < 8; i++) c1p[i] = (const float*)d_in[4 + i];
    const float* c2p[8]; for (int i = 0; i < 8; i++) c2p[i] = (const float*)d_in[12 + i];
    const float* c3p[8]; for (int i = 0; i < 8; i++) c3p[i] = (const float*)d_in[20 + i];
    const float* fc1W = (const float*)d_in[28];
    const float* fc1b = (const float*)d_in[29];
    const float* fc2W = (const float*)d_in[30];
    const float* fc2b = (const float*)d_in[31];
    float* out = (float*)d_out;

    float *agg_p, *hA_p, *hB_p;
    cudaGetSymbolAddress((void**)&agg_p, g_agg);
    cudaGetSymbolAddress((void**)&hA_p, g_hA);
    cudaGetSymbolAddress((void**)&hB_p, g_hB);

    const int TPB = 256;
    int blkN = (NN + TPB - 1) / TPB;          // 391
    int blkE = (EE + TPB - 1) / TPB;          // 12500
    int blkW = (NN * 32 + TPB - 1) / TPB;     // 12500 (warp per node)
    int blkM = (NN + 63) / 64;                // 1563

    // CSR build
    init_zero_kernel<<<blkN, TPB>>>();
    hist_kernel<<<blkE, TPB>>>(dst);
    scan_kernel<<<1, 1024>>>();
    cursor_kernel<<<blkN, TPB>>>();
    scatter_kernel<<<blkE, TPB>>>(src, dst);

    // layer 1 (F=13 -> 64)
    agg_kernel<FF><<<blkW, TPB>>>(x, agg_p);
    mlp_kernel<FF><<<blkM, TPB>>>(agg_p, c1p[0], c1p[1], c1p[2], c1p[3], c1p[4], c1p[5],
                                  c1p[6], c1p[7], batch, hA_p, 0);
    // layer 2 (64 -> 64)
    agg_kernel<HH><<<blkW, TPB>>>(hA_p, agg_p);
    mlp_kernel<HH><<<blkM, TPB>>>(agg_p, c2p[0], c2p[1], c2p[2], c2p[3], c2p[4], c2p[5],
                                  c2p[6], c2p[7], batch, hB_p, 64);
    // layer 3 (64 -> 64)
    agg_kernel<HH><<<blkW, TPB>>>(hB_p, agg_p);
    mlp_kernel<HH><<<blkM, TPB>>>(agg_p, c3p[0], c3p[1], c3p[2], c3p[3], c3p[4], c3p[5],
                                  c3p[6], c3p[7], batch, hA_p, 128);

    // readout head
    head_kernel<<<GG, POOLW>>>(fc1W, fc1b, fc2W, fc2b, out);
}

// round 4
// speedup vs baseline: 1.1350x; 1.1350x over previous
#include <cuda_runtime.h>
#include <math.h>

#define NN 100000
#define EE 3200000
#define FF 13
#define HH 64
#define GG 512
#define POOLW 192
#define BN_EPS 1e-5f

// ---------------- scratch (device globals: allocation-free) ----------------
__device__ int   g_deg[NN];
__device__ int   g_rowptr[NN + 1];
__device__ int   g_cursor[NN];
__device__ int   g_col[EE];
__device__ float g_hA[NN * 64];
__device__ float g_hB[NN * 64];
__device__ float g_pool[GG * POOLW];

// ---------------- CSR build ----------------
__global__ void init_zero_kernel() {
    int i = blockIdx.x * blockDim.x + threadIdx.x;
    if (i < NN) g_deg[i] = 0;
    if (i < GG * POOLW) g_pool[i] = 0.f;
}

__global__ void hist_kernel(const int* __restrict__ dst) {
    int i = blockIdx.x * blockDim.x + threadIdx.x;
    if (i < EE) atomicAdd(&g_deg[dst[i]], 1);
}

// Single-block looped exclusive scan over g_deg -> g_rowptr (+ cursor copy fused)
__global__ void scan_kernel() {
    __shared__ int wsum[32];
    __shared__ int carry;
    int tid = threadIdx.x;
    if (tid == 0) carry = 0;
    __syncthreads();
    for (int base = 0; base < NN; base += 1024) {
        int i = base + tid;
        int v = (i < NN) ? g_deg[i] : 0;
        int x = v;
#pragma unroll
        for (int o = 1; o < 32; o <<= 1) {
            int y = __shfl_up_sync(0xffffffffu, x, o);
            if ((tid & 31) >= o) x += y;
        }
        if ((tid & 31) == 31) wsum[tid >> 5] = x;
        __syncthreads();
        if (tid < 32) {
            int s = wsum[tid];
            int xs = s;
#pragma unroll
            for (int o = 1; o < 32; o <<= 1) {
                int y = __shfl_up_sync(0xffffffffu, xs, o);
                if (tid >= o) xs += y;
            }
            wsum[tid] = xs - s;
        }
        __syncthreads();
        int incl = x + wsum[tid >> 5] + carry;
        if (i < NN) {
            int excl = incl - v;
            g_rowptr[i] = excl;
            g_cursor[i] = excl;   // fused cursor init (was a separate kernel)
        }
        __syncthreads();
        if (tid == 1023) carry = incl;
        __syncthreads();
    }
    if (tid == 0) g_rowptr[NN] = carry;
}

__global__ void scatter_kernel(const int* __restrict__ src, const int* __restrict__ dst) {
    int i = blockIdx.x * blockDim.x + threadIdx.x;
    if (i < EE) {
        int p = atomicAdd(&g_cursor[dst[i]], 1);
        g_col[p] = src[i];
    }
}

// ---------------- fused GIN layer: CSR gather-sum + MLP + pooled readout ----------------
// 64-node tile, 256 threads. smem: As (64x64) + W1s (64x64, reused as output
// staging for pool reduction) + W2s (64x64) = exactly 48KB static.
template <int FIN>
__global__ void __launch_bounds__(256)
gin_layer_kernel(const float* __restrict__ xin,
                 const float* __restrict__ W1, const float* __restrict__ b1,
                 const float* __restrict__ gam, const float* __restrict__ bet,
                 const float* __restrict__ mu, const float* __restrict__ var,
                 const float* __restrict__ W2, const float* __restrict__ b2,
                 const int* __restrict__ batch,
                 float* __restrict__ hout, int pool_off) {
    constexpr int KPAD = (FIN == 13) ? 16 : 64;
    __shared__ float As[64 * 64];    // gathered input tile, later T (hidden acts)
    __shared__ float W1s[64 * 64];   // W1, later output staging for pooling
    __shared__ float W2s[64 * 64];
    __shared__ int   bgid[64];

    int tid = threadIdx.x;
    int node0 = blockIdx.x * 64;
    int warp = tid >> 5, lane = tid & 31;

    // ---- load weights (zero-pad W1 rows FIN..KPAD to keep 0*garbage clean) ----
    for (int idx = tid; idx < KPAD * 64; idx += 256)
        W1s[idx] = (idx < FIN * 64) ? W1[idx] : 0.f;
    for (int idx = tid; idx < 64 * 64; idx += 256) W2s[idx] = W2[idx];
    if (tid < 64) {
        int node = node0 + tid;
        bgid[tid] = batch[(node < NN) ? node : (NN - 1)];
    }

    // ---- gather phase: warp w handles nodes w*8 .. w*8+7 ----
    // col indices loaded coalesced (32/warp-LDG), broadcast via shfl, 4
    // independent row gathers in flight per step -> LTS-BW bound, not lat bound.
#pragma unroll 1
    for (int i = 0; i < 8; i++) {
        int r = warp * 8 + i;
        int node = node0 + r;
        if (FIN == 13) {
            float acc = 0.f;
            if (node < NN && lane < FF) acc = xin[node * FF + lane];
            if (node < NN) {
                int s = g_rowptr[node], e = g_rowptr[node + 1];
                for (int base = s; base < e; base += 32) {
                    int cnt = min(32, e - base);
                    int cidx = (lane < cnt) ? g_col[base + lane] : 0;
                    int t = 0;
                    for (; t + 4 <= cnt; t += 4) {
                        int j0 = __shfl_sync(0xffffffffu, cidx, t);
                        int j1 = __shfl_sync(0xffffffffu, cidx, t + 1);
                        int j2 = __shfl_sync(0xffffffffu, cidx, t + 2);
                        int j3 = __shfl_sync(0xffffffffu, cidx, t + 3);
                        if (lane < FF) {
                            float v0 = xin[j0 * FF + lane];
                            float v1 = xin[j1 * FF + lane];
                            float v2 = xin[j2 * FF + lane];
                            float v3 = xin[j3 * FF + lane];
                            acc += (v0 + v1) + (v2 + v3);
                        }
                    }
                    for (; t < cnt; t++) {
                        int j = __shfl_sync(0xffffffffu, cidx, t);
                        if (lane < FF) acc += xin[j * FF + lane];
                    }
                }
            }
            if (lane < 16) As[r * 64 + lane] = (lane < FF) ? acc : 0.f;
        } else {
            float2 acc = make_float2(0.f, 0.f);
            if (node < NN) {
                acc = ((const float2*)(xin + (size_t)node * 64))[lane];
                int s = g_rowptr[node], e = g_rowptr[node + 1];
                for (int base = s; base < e; base += 32) {
                    int cnt = min(32, e - base);
                    int cidx = (lane < cnt) ? g_col[base + lane] : 0;
                    int t = 0;
                    for (; t + 4 <= cnt; t += 4) {
                        int j0 = __shfl_sync(0xffffffffu, cidx, t);
                        int j1 = __shfl_sync(0xffffffffu, cidx, t + 1);
                        int j2 = __shfl_sync(0xffffffffu, cidx, t + 2);
                        int j3 = __shfl_sync(0xffffffffu, cidx, t + 3);
                        float2 v0 = ((const float2*)(xin + (size_t)j0 * 64))[lane];
                        float2 v1 = ((const float2*)(xin + (size_t)j1 * 64))[lane];
                        float2 v2 = ((const float2*)(xin + (size_t)j2 * 64))[lane];
                        float2 v3 = ((const float2*)(xin + (size_t)j3 * 64))[lane];
                        acc.x += (v0.x + v1.x) + (v2.x + v3.x);
                        acc.y += (v0.y + v1.y) + (v2.y + v3.y);
                    }
                    for (; t < cnt; t++) {
                        int j = __shfl_sync(0xffffffffu, cidx, t);
                        float2 v = ((const float2*)(xin + (size_t)j * 64))[lane];
                        acc.x += v.x; acc.y += v.y;
                    }
                }
            }
            ((float2*)(As + r * 64))[lane] = acc;
        }
    }
    __syncthreads();

    // ---- GEMM1: T = A @ W1 (4x4 micro-tile, k unrolled by 4 with float4 LDS) ----
    int ty = tid >> 4, tx = tid & 15;
    int r0 = 4 * ty, c0 = 4 * tx;

    float acc[4][4];
#pragma unroll
    for (int i = 0; i < 4; i++)
#pragma unroll
        for (int j = 0; j < 4; j++) acc[i][j] = 0.f;

#pragma unroll
    for (int k = 0; k < KPAD; k += 4) {
        float4 a[4], b[4];
#pragma unroll
        for (int i = 0; i < 4; i++) a[i] = *(const float4*)&As[(r0 + i) * 64 + k];
#pragma unroll
        for (int kk = 0; kk < 4; kk++) b[kk] = *(const float4*)&W1s[(k + kk) * 64 + c0];
#pragma unroll
        for (int i = 0; i < 4; i++) {
            acc[i][0] = fmaf(a[i].x, b[0].x, acc[i][0]);
            acc[i][1] = fmaf(a[i].x, b[0].y, acc[i][1]);
            acc[i][2] = fmaf(a[i].x, b[0].z, acc[i][2]);
            acc[i][3] = fmaf(a[i].x, b[0].w, acc[i][3]);
            acc[i][0] = fmaf(a[i].y, b[1].x, acc[i][0]);
            acc[i][1] = fmaf(a[i].y, b[1].y, acc[i][1]);
            acc[i][2] = fmaf(a[i].y, b[1].z, acc[i][2]);
            acc[i][3] = fmaf(a[i].y, b[1].w, acc[i][3]);
            acc[i][0] = fmaf(a[i].z, b[2].x, acc[i][0]);
            acc[i][1] = fmaf(a[i].z, b[2].y, acc[i][1]);
            acc[i][2] = fmaf(a[i].z, b[2].z, acc[i][2]);
            acc[i][3] = fmaf(a[i].z, b[2].w, acc[i][3]);
            acc[i][0] = fmaf(a[i].w, b[3].x, acc[i][0]);
            acc[i][1] = fmaf(a[i].w, b[3].y, acc[i][1]);
            acc[i][2] = fmaf(a[i].w, b[3].z, acc[i][2]);
            acc[i][3] = fmaf(a[i].w, b[3].w, acc[i][3]);
        }
    }

    // +b1 -> BatchNorm (running stats) -> ReLU
    float t1[4][4];
#pragma unroll
    for (int j = 0; j < 4; j++) {
        int col = c0 + j;
        float s = gam[col] * rsqrtf(var[col] + BN_EPS);
        float bb = bet[col] - mu[col] * s;
        float bias = b1[col];
#pragma unroll
        for (int i = 0; i < 4; i++)
            t1[i][j] = fmaxf(fmaf(acc[i][j] + bias, s, bb), 0.f);
    }
    __syncthreads();
#pragma unroll
    for (int i = 0; i < 4; i++)
        *(float4*)&As[(r0 + i) * 64 + c0] = make_float4(t1[i][0], t1[i][1], t1[i][2], t1[i][3]);
    __syncthreads();

    // ---- GEMM2: O = T @ W2 ----
    float acc2[4][4];
#pragma unroll
    for (int i = 0; i < 4; i++)
#pragma unroll
        for (int j = 0; j < 4; j++) acc2[i][j] = 0.f;

#pragma unroll
    for (int k = 0; k < 64; k += 4) {
        float4 a[4], b[4];
#pragma unroll
        for (int i = 0; i < 4; i++) a[i] = *(const float4*)&As[(r0 + i) * 64 + k];
#pragma unroll
        for (int kk = 0; kk < 4; kk++) b[kk] = *(const float4*)&W2s[(k + kk) * 64 + c0];
#pragma unroll
        for (int i = 0; i < 4; i++) {
            acc2[i][0] = fmaf(a[i].x, b[0].x, acc2[i][0]);
            acc2[i][1] = fmaf(a[i].x, b[0].y, acc2[i][1]);
            acc2[i][2] = fmaf(a[i].x, b[0].z, acc2[i][2]);
            acc2[i][3] = fmaf(a[i].x, b[0].w, acc2[i][3]);
            acc2[i][0] = fmaf(a[i].y, b[1].x, acc2[i][0]);
            acc2[i][1] = fmaf(a[i].y, b[1].y, acc2[i][1]);
            acc2[i][2] = fmaf(a[i].y, b[1].z, acc2[i][2]);
            acc2[i][3] = fmaf(a[i].y, b[1].w, acc2[i][3]);
            acc2[i][0] = fmaf(a[i].z, b[2].x, acc2[i][0]);
            acc2[i][1] = fmaf(a[i].z, b[2].y, acc2[i][1]);
            acc2[i][2] = fmaf(a[i].z, b[2].z, acc2[i][2]);
            acc2[i][3] = fmaf(a[i].z, b[2].w, acc2[i][3]);
            acc2[i][0] = fmaf(a[i].w, b[3].x, acc2[i][0]);
            acc2[i][1] = fmaf(a[i].w, b[3].y, acc2[i][1]);
            acc2[i][2] = fmaf(a[i].w, b[3].z, acc2[i][2]);
            acc2[i][3] = fmaf(a[i].w, b[3].w, acc2[i][3]);
        }
    }

    // ---- epilogue: +b2, ReLU, write h_out (float4), stage for pool reduce ----
#pragma unroll
    for (int i = 0; i < 4; i++) {
        int node = node0 + r0 + i;
        float4 o;
        o.x = fmaxf(acc2[i][0] + b2[c0 + 0], 0.f);
        o.y = fmaxf(acc2[i][1] + b2[c0 + 1], 0.f);
        o.z = fmaxf(acc2[i][2] + b2[c0 + 2], 0.f);
        o.w = fmaxf(acc2[i][3] + b2[c0 + 3], 0.f);
        if (node >= NN) o = make_float4(0.f, 0.f, 0.f, 0.f);
        else *(float4*)&hout[(size_t)node * 64 + c0] = o;
        *(float4*)&W1s[(r0 + i) * 64 + c0] = o;   // staging (W1s dead after GEMM1)
    }
    __syncthreads();

    // ---- pooled readout: batch is SORTED -> few gid runs per 64-node tile.
    // 4 threads per column, each reduces a 16-row segment run-wise.
    {
        int col = tid & 63;
        int seg = tid >> 6;          // 0..3
        int rbeg = seg * 16;
        int cur = bgid[rbeg];
        float run = 0.f;
#pragma unroll
        for (int r = rbeg; r < rbeg + 16; r++) {
            int gid = bgid[r];
            if (gid != cur) {
                atomicAdd(&g_pool[cur * POOLW + pool_off + col], run);
                run = 0.f; cur = gid;
            }
            run += W1s[r * 64 + col];
        }
        atomicAdd(&g_pool[cur * POOLW + pool_off + col], run);
    }
}

// ---------------- head: fc1(192->192)+ReLU, fc2(192->2), log_softmax ----------------
__global__ void head_kernel(const float* __restrict__ fc1W, const float* __restrict__ fc1b,
                            const float* __restrict__ fc2W, const float* __restrict__ fc2b,
                            float* __restrict__ out) {
    __shared__ float h[POOLW];
    __shared__ float h2[POOLW];
    __shared__ float r0s[6], r1s[6];
    int g = blockIdx.x, t = threadIdx.x;
    h[t] = g_pool[g * POOLW + t];
    __syncthreads();
    float acc = fc1b[t];
#pragma unroll 8
    for (int k = 0; k < POOLW; k++) acc = fmaf(h[k], fc1W[k * POOLW + t], acc);
    h2[t] = fmaxf(acc, 0.f);
    __syncthreads();
    float p0 = h2[t] * fc2W[t * 2 + 0];
    float p1 = h2[t] * fc2W[t * 2 + 1];
#pragma unroll
    for (int o = 16; o > 0; o >>= 1) {
        p0 += __shfl_down_sync(0xffffffffu, p0, o);
        p1 += __shfl_down_sync(0xffffffffu, p1, o);
    }
    if ((t & 31) == 0) { r0s[t >> 5] = p0; r1s[t >> 5] = p1; }
    __syncthreads();
    if (t == 0) {
        float z0 = fc2b[0], z1 = fc2b[1];
#pragma unroll
        for (int w = 0; w < 6; w++) { z0 += r0s[w]; z1 += r1s[w]; }
        float mx = fmaxf(z0, z1);
        float lse = mx + logf(expf(z0 - mx) + expf(z1 - mx));
        out[g * 2 + 0] = z0 - lse;
        out[g * 2 + 1] = z1 - lse;
    }
}

// ---------------- launch ----------------
extern "C" void kernel_launch(void* const* d_in, const int* in_sizes, int n_in,
                              void* d_out, int out_size) {
    const float* x     = (const float*)d_in[0];
    const int*   src   = (const int*)d_in[1];
    const int*   dst   = (const int*)d_in[2];
    const int*   batch = (const int*)d_in[3];

    const float* c1p[8]; for (int i = 0; i < 8; i++) c1p[i] = (const float*)d_in[4 + i];
    const float* c2p[8]; for (int i = 0; i < 8; i++) c2p[i] = (const float*)d_in[12 + i];
    const float* c3p[8]; for (int i = 0; i < 8; i++) c3p[i] = (const float*)d_in[20 + i];
    const float* fc1W = (const float*)d_in[28];
    const float* fc1b = (const float*)d_in[29];
    const float* fc2W = (const float*)d_in[30];
    const float* fc2b = (const float*)d_in[31];
    float* out = (float*)d_out;

    float *hA_p, *hB_p;
    cudaGetSymbolAddress((void**)&hA_p, g_hA);
    cudaGetSymbolAddress((void**)&hB_p, g_hB);

    const int TPB = 256;
    int blkN = (NN + TPB - 1) / TPB;          // 391
    int blkE = (EE + TPB - 1) / TPB;          // 12500
    int blkM = (NN + 63) / 64;                // 1563

    // CSR build
    init_zero_kernel<<<blkN, TPB>>>();
    hist_kernel<<<blkE, TPB>>>(dst);
    scan_kernel<<<1, 1024>>>();
    scatter_kernel<<<blkE, TPB>>>(src, dst);

    // fused GIN layers (gather + MLP + pooling in one kernel each)
    gin_layer_kernel<FF><<<blkM, TPB>>>(x,    c1p[0], c1p[1], c1p[2], c1p[3], c1p[4], c1p[5],
                                        c1p[6], c1p[7], batch, hA_p, 0);
    gin_layer_kernel<HH><<<blkM, TPB>>>(hA_p, c2p[0], c2p[1], c2p[2], c2p[3], c2p[4], c2p[5],
                                        c2p[6], c2p[7], batch, hB_p, 64);
    gin_layer_kernel<HH><<<blkM, TPB>>>(hB_p, c3p[0], c3p[1], c3p[2], c3p[3], c3p[4], c3p[5],
                                        c3p[6], c3p[7], batch, hA_p, 128);

    // readout head
    head_kernel<<<GG, POOLW>>>(fc1W, fc1b, fc2W, fc2b, out);
}

// round 5
// speedup vs baseline: 1.1538x; 1.0165x over previous
#include <cuda_runtime.h>
#include <cuda_fp16.h>
#include <math.h>

#define NN 100000
#define EE 3200000
#define FF 13
#define HH 64
#define GG 512
#define POOLW 192
#define BN_EPS 1e-5f

// ---------------- scratch (device globals: allocation-free) ----------------
__device__ int    g_deg[NN];
__device__ int    g_rowptr[NN + 1];
__device__ int    g_cursor[NN];
__device__ int    g_col[EE];
__device__ __half g_hA[NN * 64];   // fp16 layer outputs: halves L2 gather traffic
__device__ __half g_hB[NN * 64];
__device__ float  g_pool[GG * POOLW];

// ---------------- CSR build ----------------
__global__ void init_zero_kernel() {
    int i = blockIdx.x * blockDim.x + threadIdx.x;
    if (i < NN) g_deg[i] = 0;
    if (i < GG * POOLW) g_pool[i] = 0.f;
}

__global__ void hist_kernel(const int* __restrict__ dst) {
    int i = (blockIdx.x * blockDim.x + threadIdx.x) * 2;
    if (i + 1 < EE) {
        int2 d = *(const int2*)&dst[i];
        atomicAdd(&g_deg[d.x], 1);
        atomicAdd(&g_deg[d.y], 1);
    } else if (i < EE) {
        atomicAdd(&g_deg[dst[i]], 1);
    }
}

// Single-block looped exclusive scan over g_deg -> g_rowptr (+ cursor copy fused)
__global__ void scan_kernel() {
    __shared__ int wsum[32];
    __shared__ int carry;
    int tid = threadIdx.x;
    if (tid == 0) carry = 0;
    __syncthreads();
    for (int base = 0; base < NN; base += 1024) {
        int i = base + tid;
        int v = (i < NN) ? g_deg[i] : 0;
        int x = v;
#pragma unroll
        for (int o = 1; o < 32; o <<= 1) {
            int y = __shfl_up_sync(0xffffffffu, x, o);
            if ((tid & 31) >= o) x += y;
        }
        if ((tid & 31) == 31) wsum[tid >> 5] = x;
        __syncthreads();
        if (tid < 32) {
            int s = wsum[tid];
            int xs = s;
#pragma unroll
            for (int o = 1; o < 32; o <<= 1) {
                int y = __shfl_up_sync(0xffffffffu, xs, o);
                if (tid >= o) xs += y;
            }
            wsum[tid] = xs - s;
        }
        __syncthreads();
        int incl = x + wsum[tid >> 5] + carry;
        if (i < NN) {
            int excl = incl - v;
            g_rowptr[i] = excl;
            g_cursor[i] = excl;
        }
        __syncthreads();
        if (tid == 1023) carry = incl;
        __syncthreads();
    }
    if (tid == 0) g_rowptr[NN] = carry;
}

__global__ void scatter_kernel(const int* __restrict__ src, const int* __restrict__ dst) {
    int i = (blockIdx.x * blockDim.x + threadIdx.x) * 2;
    if (i + 1 < EE) {
        int2 d = *(const int2*)&dst[i];
        int2 s = *(const int2*)&src[i];
        int p0 = atomicAdd(&g_cursor[d.x], 1);
        int p1 = atomicAdd(&g_cursor[d.y], 1);
        g_col[p0] = s.x;
        g_col[p1] = s.y;
    } else if (i < EE) {
        int p = atomicAdd(&g_cursor[dst[i]], 1);
        g_col[p] = src[i];
    }
}

// ---------------- fused GIN layer: CSR gather-sum + MLP + pooled readout ----------------
// 64-node tile, 256 threads. smem: As (64x64) + W1s (64x64, reused as output
// staging for pool reduction) + W2s (64x64) = exactly 48KB static.
// HALF_IN: input activations stored fp16 (layers 2,3); accumulation in fp32.
template <int FIN, bool HALF_IN>
__global__ void __launch_bounds__(256)
gin_layer_kernel(const void* __restrict__ xin_v,
                 const float* __restrict__ W1, const float* __restrict__ b1,
                 const float* __restrict__ gam, const float* __restrict__ bet,
                 const float* __restrict__ mu, const float* __restrict__ var,
                 const float* __restrict__ W2, const float* __restrict__ b2,
                 const int* __restrict__ batch,
                 __half* __restrict__ hout, int pool_off) {
    constexpr int KPAD = (FIN == 13) ? 16 : 64;
    __shared__ float As[64 * 64];    // gathered input tile, later T (hidden acts)
    __shared__ float W1s[64 * 64];   // W1, later output staging for pooling
    __shared__ float W2s[64 * 64];
    __shared__ int   bgid[64];

    int tid = threadIdx.x;
    int node0 = blockIdx.x * 64;
    int warp = tid >> 5, lane = tid & 31;

    // ---- load weights (zero-pad W1 rows FIN..KPAD) ----
    for (int idx = tid; idx < KPAD * 64; idx += 256)
        W1s[idx] = (idx < FIN * 64) ? W1[idx] : 0.f;
    for (int idx = tid; idx < 64 * 64; idx += 256) W2s[idx] = W2[idx];
    if (tid < 64) {
        int node = node0 + tid;
        bgid[tid] = batch[(node < NN) ? node : (NN - 1)];
    }

    // ---- gather phase: warp w handles nodes w*8 .. w*8+7 ----
#pragma unroll 1
    for (int i = 0; i < 8; i++) {
        int r = warp * 8 + i;
        int node = node0 + r;
        if (FIN == 13) {
            const float* xin = (const float*)xin_v;
            float acc = 0.f;
            if (node < NN && lane < FF) acc = xin[node * FF + lane];
            if (node < NN) {
                int s = g_rowptr[node], e = g_rowptr[node + 1];
                for (int base = s; base < e; base += 32) {
                    int cnt = min(32, e - base);
                    int cidx = (lane < cnt) ? g_col[base + lane] : 0;
                    int t = 0;
                    for (; t + 4 <= cnt; t += 4) {
                        int j0 = __shfl_sync(0xffffffffu, cidx, t);
                        int j1 = __shfl_sync(0xffffffffu, cidx, t + 1);
                        int j2 = __shfl_sync(0xffffffffu, cidx, t + 2);
                        int j3 = __shfl_sync(0xffffffffu, cidx, t + 3);
                        if (lane < FF) {
                            float v0 = xin[j0 * FF + lane];
                            float v1 = xin[j1 * FF + lane];
                            float v2 = xin[j2 * FF + lane];
                            float v3 = xin[j3 * FF + lane];
                            acc += (v0 + v1) + (v2 + v3);
                        }
                    }
                    for (; t < cnt; t++) {
                        int j = __shfl_sync(0xffffffffu, cidx, t);
                        if (lane < FF) acc += xin[j * FF + lane];
                    }
                }
            }
            if (lane < 16) As[r * 64 + lane] = (lane < FF) ? acc : 0.f;
        } else {
            // fp16 input rows: 32 half2 per row, one half2 per lane (128B/row)
            const __half2* xin2 = (const __half2*)xin_v;
            float2 acc = make_float2(0.f, 0.f);
            if (node < NN) {
                acc = __half22float2(xin2[node * 32 + lane]);
                int s = g_rowptr[node], e = g_rowptr[node + 1];
                for (int base = s; base < e; base += 32) {
                    int cnt = min(32, e - base);
                    int cidx = (lane < cnt) ? g_col[base + lane] : 0;
                    int t = 0;
                    for (; t + 4 <= cnt; t += 4) {
                        int j0 = __shfl_sync(0xffffffffu, cidx, t);
                        int j1 = __shfl_sync(0xffffffffu, cidx, t + 1);
                        int j2 = __shfl_sync(0xffffffffu, cidx, t + 2);
                        int j3 = __shfl_sync(0xffffffffu, cidx, t + 3);
                        float2 v0 = __half22float2(xin2[j0 * 32 + lane]);
                        float2 v1 = __half22float2(xin2[j1 * 32 + lane]);
                        float2 v2 = __half22float2(xin2[j2 * 32 + lane]);
                        float2 v3 = __half22float2(xin2[j3 * 32 + lane]);
                        acc.x += (v0.x + v1.x) + (v2.x + v3.x);
                        acc.y += (v0.y + v1.y) + (v2.y + v3.y);
                    }
                    for (; t < cnt; t++) {
                        int j = __shfl_sync(0xffffffffu, cidx, t);
                        float2 v = __half22float2(xin2[j * 32 + lane]);
                        acc.x += v.x; acc.y += v.y;
                    }
                }
            }
            ((float2*)(As + r * 64))[lane] = acc;
        }
    }
    __syncthreads();

    // ---- GEMM1: T = A @ W1 (4x4 micro-tile, k unrolled by 4, float4 LDS) ----
    int ty = tid >> 4, tx = tid & 15;
    int r0 = 4 * ty, c0 = 4 * tx;

    float acc[4][4];
#pragma unroll
    for (int i = 0; i < 4; i++)
#pragma unroll
        for (int j = 0; j < 4; j++) acc[i][j] = 0.f;

#pragma unroll
    for (int k = 0; k < KPAD; k += 4) {
        float4 a[4], b[4];
#pragma unroll
        for (int i = 0; i < 4; i++) a[i] = *(const float4*)&As[(r0 + i) * 64 + k];
#pragma unroll
        for (int kk = 0; kk < 4; kk++) b[kk] = *(const float4*)&W1s[(k + kk) * 64 + c0];
#pragma unroll
        for (int i = 0; i < 4; i++) {
            acc[i][0] = fmaf(a[i].x, b[0].x, acc[i][0]);
            acc[i][1] = fmaf(a[i].x, b[0].y, acc[i][1]);
            acc[i][2] = fmaf(a[i].x, b[0].z, acc[i][2]);
            acc[i][3] = fmaf(a[i].x, b[0].w, acc[i][3]);
            acc[i][0] = fmaf(a[i].y, b[1].x, acc[i][0]);
            acc[i][1] = fmaf(a[i].y, b[1].y, acc[i][1]);
            acc[i][2] = fmaf(a[i].y, b[1].z, acc[i][2]);
            acc[i][3] = fmaf(a[i].y, b[1].w, acc[i][3]);
            acc[i][0] = fmaf(a[i].z, b[2].x, acc[i][0]);
            acc[i][1] = fmaf(a[i].z, b[2].y, acc[i][1]);
            acc[i][2] = fmaf(a[i].z, b[2].z, acc[i][2]);
            acc[i][3] = fmaf(a[i].z, b[2].w, acc[i][3]);
            acc[i][0] = fmaf(a[i].w, b[3].x, acc[i][0]);
            acc[i][1] = fmaf(a[i].w, b[3].y, acc[i][1]);
            acc[i][2] = fmaf(a[i].w, b[3].z, acc[i][2]);
            acc[i][3] = fmaf(a[i].w, b[3].w, acc[i][3]);
        }
    }

    // +b1 -> BatchNorm (running stats) -> ReLU
    float t1[4][4];
#pragma unroll
    for (int j = 0; j < 4; j++) {
        int col = c0 + j;
        float s = gam[col] * rsqrtf(var[col] + BN_EPS);
        float bb = bet[col] - mu[col] * s;
        float bias = b1[col];
#pragma unroll
        for (int i = 0; i < 4; i++)
            t1[i][j] = fmaxf(fmaf(acc[i][j] + bias, s, bb), 0.f);
    }
    __syncthreads();
#pragma unroll
    for (int i = 0; i < 4; i++)
        *(float4*)&As[(r0 + i) * 64 + c0] = make_float4(t1[i][0], t1[i][1], t1[i][2], t1[i][3]);
    __syncthreads();

    // ---- GEMM2: O = T @ W2 ----
    float acc2[4][4];
#pragma unroll
    for (int i = 0; i < 4; i++)
#pragma unroll
        for (int j = 0; j < 4; j++) acc2[i][j] = 0.f;

#pragma unroll
    for (int k = 0; k < 64; k += 4) {
        float4 a[4], b[4];
#pragma unroll
        for (int i = 0; i < 4; i++) a[i] = *(const float4*)&As[(r0 + i) * 64 + k];
#pragma unroll
        for (int kk = 0; kk < 4; kk++) b[kk] = *(const float4*)&W2s[(k + kk) * 64 + c0];
#pragma unroll
        for (int i = 0; i < 4; i++) {
            acc2[i][0] = fmaf(a[i].x, b[0].x, acc2[i][0]);
            acc2[i][1] = fmaf(a[i].x, b[0].y, acc2[i][1]);
            acc2[i][2] = fmaf(a[i].x, b[0].z, acc2[i][2]);
            acc2[i][3] = fmaf(a[i].x, b[0].w, acc2[i][3]);
            acc2[i][0] = fmaf(a[i].y, b[1].x, acc2[i][0]);
            acc2[i][1] = fmaf(a[i].y, b[1].y, acc2[i][1]);
            acc2[i][2] = fmaf(a[i].y, b[1].z, acc2[i][2]);
            acc2[i][3] = fmaf(a[i].y, b[1].w, acc2[i][3]);
            acc2[i][0] = fmaf(a[i].z, b[2].x, acc2[i][0]);
            acc2[i][1] = fmaf(a[i].z, b[2].y, acc2[i][1]);
            acc2[i][2] = fmaf(a[i].z, b[2].z, acc2[i][2]);
            acc2[i][3] = fmaf(a[i].z, b[2].w, acc2[i][3]);
            acc2[i][0] = fmaf(a[i].w, b[3].x, acc2[i][0]);
            acc2[i][1] = fmaf(a[i].w, b[3].y, acc2[i][1]);
            acc2[i][2] = fmaf(a[i].w, b[3].z, acc2[i][2]);
            acc2[i][3] = fmaf(a[i].w, b[3].w, acc2[i][3]);
        }
    }

    // ---- epilogue: +b2, ReLU, write fp16 h_out (8B packed), stage for pool ----
#pragma unroll
    for (int i = 0; i < 4; i++) {
        int node = node0 + r0 + i;
        float4 o;
        o.x = fmaxf(acc2[i][0] + b2[c0 + 0], 0.f);
        o.y = fmaxf(acc2[i][1] + b2[c0 + 1], 0.f);
        o.z = fmaxf(acc2[i][2] + b2[c0 + 2], 0.f);
        o.w = fmaxf(acc2[i][3] + b2[c0 + 3], 0.f);
        if (node >= NN) o = make_float4(0.f, 0.f, 0.f, 0.f);
        else {
            __half2 p0 = __floats2half2_rn(o.x, o.y);
            __half2 p1 = __floats2half2_rn(o.z, o.w);
            uint2 pk;
            pk.x = *(unsigned int*)&p0;
            pk.y = *(unsigned int*)&p1;
            *(uint2*)&hout[(size_t)node * 64 + c0] = pk;
        }
        *(float4*)&W1s[(r0 + i) * 64 + c0] = o;   // staging (W1s dead after GEMM1)
    }
    __syncthreads();

    // ---- pooled readout: batch is SORTED -> few gid runs per 64-node tile. ----
    {
        int col = tid & 63;
        int seg = tid >> 6;          // 0..3
        int rbeg = seg * 16;
        int cur = bgid[rbeg];
        float run = 0.f;
#pragma unroll
        for (int r = rbeg; r < rbeg + 16; r++) {
            int gid = bgid[r];
            if (gid != cur) {
                atomicAdd(&g_pool[cur * POOLW + pool_off + col], run);
                run = 0.f; cur = gid;
            }
            run += W1s[r * 64 + col];
        }
        atomicAdd(&g_pool[cur * POOLW + pool_off + col], run);
    }
}

// ---------------- head: fc1(192->192)+ReLU, fc2(192->2), log_softmax ----------------
__global__ void head_kernel(const float* __restrict__ fc1W, const float* __restrict__ fc1b,
                            const float* __restrict__ fc2W, const float* __restrict__ fc2b,
                            float* __restrict__ out) {
    __shared__ float h[POOLW];
    __shared__ float h2[POOLW];
    __shared__ float r0s[6], r1s[6];
    int g = blockIdx.x, t = threadIdx.x;
    h[t] = g_pool[g * POOLW + t];
    __syncthreads();
    float acc = fc1b[t];
#pragma unroll 8
    for (int k = 0; k < POOLW; k++) acc = fmaf(h[k], fc1W[k * POOLW + t], acc);
    h2[t] = fmaxf(acc, 0.f);
    __syncthreads();
    float p0 = h2[t] * fc2W[t * 2 + 0];
    float p1 = h2[t] * fc2W[t * 2 + 1];
#pragma unroll
    for (int o = 16; o > 0; o >>= 1) {
        p0 += __shfl_down_sync(0xffffffffu, p0, o);
        p1 += __shfl_down_sync(0xffffffffu, p1, o);
    }
    if ((t & 31) == 0) { r0s[t >> 5] = p0; r1s[t >> 5] = p1; }
    __syncthreads();
    if (t == 0) {
        float z0 = fc2b[0], z1 = fc2b[1];
#pragma unroll
        for (int w = 0; w < 6; w++) { z0 += r0s[w]; z1 += r1s[w]; }
        float mx = fmaxf(z0, z1);
        float lse = mx + logf(expf(z0 - mx) + expf(z1 - mx));
        out[g * 2 + 0] = z0 - lse;
        out[g * 2 + 1] = z1 - lse;
    }
}

// ---------------- launch ----------------
extern "C" void kernel_launch(void* const* d_in, const int* in_sizes, int n_in,
                              void* d_out, int out_size) {
    const float* x     = (const float*)d_in[0];
    const int*   src   = (const int*)d_in[1];
    const int*   dst   = (const int*)d_in[2];
    const int*   batch = (const int*)d_in[3];

    const float* c1p[8]; for (int i = 0; i < 8; i++) c1p[i] = (const float*)d_in[4 + i];
    const float* c2p[8]; for (int i = 0; i < 8; i++) c2p[i] = (const float*)d_in[12 + i];
    const float* c3p[8]; for (int i = 0; i < 8; i++) c3p[i] = (const float*)d_in[20 + i];
    const float* fc1W = (const float*)d_in[28];
    const float* fc1b = (const float*)d_in[29];
    const float* fc2W = (const float*)d_in[30];
    const float* fc2b = (const float*)d_in[31];
    float* out = (float*)d_out;

    __half *hA_p, *hB_p;
    cudaGetSymbolAddress((void**)&hA_p, g_hA);
    cudaGetSymbolAddress((void**)&hB_p, g_hB);

    const int TPB = 256;
    int blkN = (NN + TPB - 1) / TPB;                // 391
    int blkE2 = (EE / 2 + TPB - 1) / TPB;           // 6250 (2 edges/thread)
    int blkM = (NN + 63) / 64;                      // 1563

    // CSR build
    init_zero_kernel<<<blkN, TPB>>>();
    hist_kernel<<<blkE2, TPB>>>(dst);
    scan_kernel<<<1, 1024>>>();
    scatter_kernel<<<blkE2, TPB>>>(src, dst);

    // fused GIN layers (gather + MLP + pooling in one kernel each)
    gin_layer_kernel<FF, false><<<blkM, TPB>>>(x,    c1p[0], c1p[1], c1p[2], c1p[3], c1p[4],
                                               c1p[5], c1p[6], c1p[7], batch, hA_p, 0);
    gin_layer_kernel<HH, true ><<<blkM, TPB>>>(hA_p, c2p[0], c2p[1], c2p[2], c2p[3], c2p[4],
                                               c2p[5], c2p[6], c2p[7], batch, hB_p, 64);
    gin_layer_kernel<HH, true ><<<blkM, TPB>>>(hB_p, c3p[0], c3p[1], c3p[2], c3p[3], c3p[4],
                                               c3p[5], c3p[6], c3p[7], batch, hA_p, 128);

    // readout head
    head_kernel<<<GG, POOLW>>>(fc1W, fc1b, fc2W, fc2b, out);
}

// round 8
// speedup vs baseline: 1.4207x; 1.2314x over previous
#include <cuda_runtime.h>
#include <cuda_fp16.h>
#include <stdint.h>
#include <math.h>

#define NN 100000
#define EE 3200000
#define FF 13
#define HH 64
#define GG 512
#define POOLW 192
#define BN_EPS 1e-5f

// ---------------- scratch (device globals: allocation-free) ----------------
__device__ int    g_deg[NN];
__device__ int    g_rowptr[NN + 1];
__device__ int    g_cursor[NN];
__device__ int    g_col[EE];
__device__ __half g_hA[NN * 64];
__device__ __half g_hB[NN * 64];
__device__ float  g_pool[GG * POOLW];

// ---------------- PTX helpers (no templates, no uint32_t, long names) ----------------
__device__ __forceinline__ void gin_ldsm_a(unsigned int* frag_out4, unsigned int smem_addr_u32) {
    asm volatile("ldmatrix.sync.aligned.m8n8.x4.shared.b16 {%0,%1,%2,%3}, [%4];"
                 : "=r"(frag_out4[0]), "=r"(frag_out4[1]),
                   "=r"(frag_out4[2]), "=r"(frag_out4[3])
                 : "r"(smem_addr_u32));
}

__device__ __forceinline__ void gin_ldsm_bt(unsigned int* frag_out4, unsigned int smem_addr_u32) {
    asm volatile("ldmatrix.sync.aligned.m8n8.x4.trans.shared.b16 {%0,%1,%2,%3}, [%4];"
                 : "=r"(frag_out4[0]), "=r"(frag_out4[1]),
                   "=r"(frag_out4[2]), "=r"(frag_out4[3])
                 : "r"(smem_addr_u32));
}

__device__ __forceinline__ void gin_mma(float* acc_inout4, const unsigned int* frag_a4,
                                        unsigned int frag_b_first, unsigned int frag_b_second) {
    asm volatile(
        "mma.sync.aligned.m16n8k16.row.col.f32.f16.f16.f32 "
        "{%0,%1,%2,%3}, {%4,%5,%6,%7}, {%8,%9}, {%0,%1,%2,%3};"
        : "+f"(acc_inout4[0]), "+f"(acc_inout4[1]),
          "+f"(acc_inout4[2]), "+f"(acc_inout4[3])
        : "r"(frag_a4[0]), "r"(frag_a4[1]), "r"(frag_a4[2]), "r"(frag_a4[3]),
          "r"(frag_b_first), "r"(frag_b_second));
}

// ---------------- CSR build ----------------
__global__ void init_zero_kernel() {
    int i = blockIdx.x * blockDim.x + threadIdx.x;
    if (i < NN) g_deg[i] = 0;
    if (i < GG * POOLW) g_pool[i] = 0.f;
}

__global__ void hist_kernel(const int* __restrict__ dst) {
    int i = (blockIdx.x * blockDim.x + threadIdx.x) * 4;
    if (i < EE) {  // EE % 4 == 0
        int4 dstv = *(const int4*)&dst[i];
        atomicAdd(&g_deg[dstv.x], 1);
        atomicAdd(&g_deg[dstv.y], 1);
        atomicAdd(&g_deg[dstv.z], 1);
        atomicAdd(&g_deg[dstv.w], 1);
    }
}

// Single-block looped exclusive scan over g_deg -> g_rowptr (+ cursor copy fused)
__global__ void scan_kernel() {
    __shared__ int wsum[32];
    __shared__ int carry;
    int tid = threadIdx.x;
    if (tid == 0) carry = 0;
    __syncthreads();
    for (int base = 0; base < NN; base += 1024) {
        int i = base + tid;
        int v = (i < NN) ? g_deg[i] : 0;
        int x = v;
#pragma unroll
        for (int o = 1; o < 32; o <<= 1) {
            int y = __shfl_up_sync(0xffffffffu, x, o);
            if ((tid & 31) >= o) x += y;
        }
        if ((tid & 31) == 31) wsum[tid >> 5] = x;
        __syncthreads();
        if (tid < 32) {
            int s = wsum[tid];
            int xs = s;
#pragma unroll
            for (int o = 1; o < 32; o <<= 1) {
                int y = __shfl_up_sync(0xffffffffu, xs, o);
                if (tid >= o) xs += y;
            }
            wsum[tid] = xs - s;
        }
        __syncthreads();
        int incl = x + wsum[tid >> 5] + carry;
        if (i < NN) {
            int excl = incl - v;
            g_rowptr[i] = excl;
            g_cursor[i] = excl;
        }
        __syncthreads();
        if (tid == 1023) carry = incl;
        __syncthreads();
    }
    if (tid == 0) g_rowptr[NN] = carry;
}

__global__ void scatter_kernel(const int* __restrict__ src, const int* __restrict__ dst) {
    int i = (blockIdx.x * blockDim.x + threadIdx.x) * 4;
    if (i < EE) {
        int4 dstv = *(const int4*)&dst[i];
        int4 srcv = *(const int4*)&src[i];
        int p0 = atomicAdd(&g_cursor[dstv.x], 1);
        int p1 = atomicAdd(&g_cursor[dstv.y], 1);
        int p2 = atomicAdd(&g_cursor[dstv.z], 1);
        int p3 = atomicAdd(&g_cursor[dstv.w], 1);
        g_col[p0] = srcv.x;
        g_col[p1] = srcv.y;
        g_col[p2] = srcv.z;
        g_col[p3] = srcv.w;
    }
}

// smem layout constants for the layer kernels
#define SMEM_ROW_H 72   /* half elements per row (144B): ldmatrix conflict-free */
#define POOL_ROW_F 68   /* float elements per row of pool staging */

// ---------------- layer 1: FIN=13 fp32 input, tensor-core MLP + pooling ----------------
__global__ void __launch_bounds__(256)
gin_layer_first_kernel(const float* __restrict__ xin,
                       const float* __restrict__ W1, const float* __restrict__ b1,
                       const float* __restrict__ gam, const float* __restrict__ bet,
                       const float* __restrict__ mu, const float* __restrict__ var,
                       const float* __restrict__ W2, const float* __restrict__ b2,
                       const int* __restrict__ batch,
                       __half* __restrict__ hout, int pool_off) {
    __shared__ __half As[64 * SMEM_ROW_H];
    __shared__ __half W1s[64 * SMEM_ROW_H];
    __shared__ __half W2s[64 * SMEM_ROW_H];
    __shared__ float  Ps[64 * POOL_ROW_F];
    __shared__ float  sc1[64], sh1[64], b2s[64];
    __shared__ int    bgid[64];

    int tid = threadIdx.x;
    int node0 = blockIdx.x * 64;
    int warp = tid >> 5, lane = tid & 31;

    // weights -> fp16 smem; W1 rows 13..15 zero-padded (KPAD=16)
    for (int idx = tid; idx < 16 * 64; idx += 256) {
        int krow = idx >> 6, ncol = idx & 63;
        W1s[krow * SMEM_ROW_H + ncol] = __float2half((krow < FF) ? W1[krow * 64 + ncol] : 0.f);
    }
    for (int idx = tid; idx < 64 * 64; idx += 256) {
        int krow = idx >> 6, ncol = idx & 63;
        W2s[krow * SMEM_ROW_H + ncol] = __float2half(W2[krow * 64 + ncol]);
    }
    if (tid < 64) {
        float bn_scale = gam[tid] * rsqrtf(var[tid] + BN_EPS);
        sc1[tid] = bn_scale;
        sh1[tid] = fmaf(b1[tid] - mu[tid], bn_scale, bet[tid]);
        b2s[tid] = b2[tid];
        int node = node0 + tid;
        bgid[tid] = batch[(node < NN) ? node : (NN - 1)];
    }

    // gather phase: warp w handles nodes w*8 .. w*8+7
#pragma unroll 1
    for (int i = 0; i < 8; i++) {
        int r = warp * 8 + i;
        int node = node0 + r;
        float acc = 0.f;
        if (node < NN && lane < FF) acc = xin[node * FF + lane];
        if (node < NN) {
            int s = g_rowptr[node], e = g_rowptr[node + 1];
            for (int base = s; base < e; base += 32) {
                int cnt = min(32, e - base);
                int cidx = (lane < cnt) ? g_col[base + lane] : 0;
                int t = 0;
                for (; t + 4 <= cnt; t += 4) {
                    int j0 = __shfl_sync(0xffffffffu, cidx, t);
                    int j1 = __shfl_sync(0xffffffffu, cidx, t + 1);
                    int j2 = __shfl_sync(0xffffffffu, cidx, t + 2);
                    int j3 = __shfl_sync(0xffffffffu, cidx, t + 3);
                    if (lane < FF) {
                        float v0 = xin[j0 * FF + lane];
                        float v1 = xin[j1 * FF + lane];
                        float v2 = xin[j2 * FF + lane];
                        float v3 = xin[j3 * FF + lane];
                        acc += (v0 + v1) + (v2 + v3);
                    }
                }
                for (; t < cnt; t++) {
                    int j = __shfl_sync(0xffffffffu, cidx, t);
                    if (lane < FF) acc += xin[j * FF + lane];
                }
            }
        }
        if (lane < 16) As[r * SMEM_ROW_H + lane] = __float2half((lane < FF) ? acc : 0.f);
    }
    __syncthreads();

    int mma_row = warp & 3;            // rows mma_row*16..+15
    int mma_col = (warp >> 2) * 32;    // 32 cols per warp
    unsigned int base_as = (unsigned int)__cvta_generic_to_shared(As);
    unsigned int base_w1 = (unsigned int)__cvta_generic_to_shared(W1s);
    unsigned int base_w2 = (unsigned int)__cvta_generic_to_shared(W2s);
    int off_a = (mma_row * 16 + (lane & 15)) * SMEM_ROW_H + ((lane >> 4) << 3);
    int off_w = (lane & 15) * SMEM_ROW_H + mma_col + ((lane >> 4) << 3);

    // GEMM1: T = A @ W1 (KPAD=16 -> single k-chunk)
    float acc1[4][4];
#pragma unroll
    for (int i = 0; i < 4; i++)
#pragma unroll
        for (int j = 0; j < 4; j++) acc1[i][j] = 0.f;
    {
        unsigned int frag_a[4];
        unsigned int frag_b_lo[4];
        unsigned int frag_b_hi[4];
        gin_ldsm_a(frag_a, base_as + (unsigned int)(off_a * 2));
        gin_ldsm_bt(frag_b_lo, base_w1 + (unsigned int)(off_w * 2));
        gin_ldsm_bt(frag_b_hi, base_w1 + (unsigned int)((off_w + 16) * 2));
        gin_mma(acc1[0], frag_a, frag_b_lo[0], frag_b_lo[1]);
        gin_mma(acc1[1], frag_a, frag_b_lo[2], frag_b_lo[3]);
        gin_mma(acc1[2], frag_a, frag_b_hi[0], frag_b_hi[1]);
        gin_mma(acc1[3], frag_a, frag_b_hi[2], frag_b_hi[3]);
    }
    __syncthreads();

    // epilogue1: BN+ReLU -> As (fp16)
    {
        int row_out = mma_row * 16 + (lane >> 2);
#pragma unroll
        for (int j = 0; j < 4; j++) {
            int c = mma_col + j * 8 + ((lane & 3) << 1);
            float o00 = fmaxf(fmaf(acc1[j][0], sc1[c],     sh1[c]),     0.f);
            float o01 = fmaxf(fmaf(acc1[j][1], sc1[c + 1], sh1[c + 1]), 0.f);
            float o10 = fmaxf(fmaf(acc1[j][2], sc1[c],     sh1[c]),     0.f);
            float o11 = fmaxf(fmaf(acc1[j][3], sc1[c + 1], sh1[c + 1]), 0.f);
            *(__half2*)&As[row_out * SMEM_ROW_H + c]       = __floats2half2_rn(o00, o01);
            *(__half2*)&As[(row_out + 8) * SMEM_ROW_H + c] = __floats2half2_rn(o10, o11);
        }
    }
    __syncthreads();

    // GEMM2: O = T @ W2 (4 k-chunks)
    float acc2[4][4];
#pragma unroll
    for (int i = 0; i < 4; i++)
#pragma unroll
        for (int j = 0; j < 4; j++) acc2[i][j] = 0.f;
#pragma unroll
    for (int kc = 0; kc < 4; kc++) {
        unsigned int frag_a[4];
        unsigned int frag_b_lo[4];
        unsigned int frag_b_hi[4];
        gin_ldsm_a(frag_a, base_as + (unsigned int)((off_a + kc * 16) * 2));
        gin_ldsm_bt(frag_b_lo, base_w2 + (unsigned int)((off_w + kc * 16 * SMEM_ROW_H) * 2));
        gin_ldsm_bt(frag_b_hi, base_w2 + (unsigned int)((off_w + kc * 16 * SMEM_ROW_H + 16) * 2));
        gin_mma(acc2[0], frag_a, frag_b_lo[0], frag_b_lo[1]);
        gin_mma(acc2[1], frag_a, frag_b_lo[2], frag_b_lo[3]);
        gin_mma(acc2[2], frag_a, frag_b_hi[0], frag_b_hi[1]);
        gin_mma(acc2[3], frag_a, frag_b_hi[2], frag_b_hi[3]);
    }

    // epilogue2: +b2, ReLU -> hout (fp16) + Ps (f32 staging)
    {
        int row_half = mma_row * 16 + (lane >> 2);
#pragma unroll
        for (int hb = 0; hb < 2; hb++) {
            int r = row_half + hb * 8;
            int node = node0 + r;
            bool valid = (node < NN);
#pragma unroll
            for (int j = 0; j < 4; j++) {
                int c = mma_col + j * 8 + ((lane & 3) << 1);
                float o0 = valid ? fmaxf(acc2[j][hb * 2 + 0] + b2s[c],     0.f) : 0.f;
                float o1 = valid ? fmaxf(acc2[j][hb * 2 + 1] + b2s[c + 1], 0.f) : 0.f;
                if (valid)
                    *(__half2*)&hout[(size_t)node * 64 + c] = __floats2half2_rn(o0, o1);
                *(float2*)&Ps[r * POOL_ROW_F + c] = make_float2(o0, o1);
            }
        }
    }
    __syncthreads();

    // pooled readout: batch is SORTED -> few gid runs per tile
    {
        int col = tid & 63;
        int seg = tid >> 6;
        int rbeg = seg * 16;
        int cur = bgid[rbeg];
        float run = 0.f;
#pragma unroll
        for (int r = rbeg; r < rbeg + 16; r++) {
            int gid = bgid[r];
            if (gid != cur) {
                atomicAdd(&g_pool[cur * POOLW + pool_off + col], run);
                run = 0.f; cur = gid;
            }
            run += Ps[r * POOL_ROW_F + col];
        }
        atomicAdd(&g_pool[cur * POOLW + pool_off + col], run);
    }
}

// ---------------- layers 2,3: FIN=64 fp16 input, tensor-core MLP + pooling ----------------
__global__ void __launch_bounds__(256)
gin_layer_hidden_kernel(const __half* __restrict__ xin,
                        const float* __restrict__ W1, const float* __restrict__ b1,
                        const float* __restrict__ gam, const float* __restrict__ bet,
                        const float* __restrict__ mu, const float* __restrict__ var,
                        const float* __restrict__ W2, const float* __restrict__ b2,
                        const int* __restrict__ batch,
                        __half* __restrict__ hout, int pool_off) {
    __shared__ __half As[64 * SMEM_ROW_H];
    __shared__ __half W1s[64 * SMEM_ROW_H];
    __shared__ __half W2s[64 * SMEM_ROW_H];
    __shared__ float  Ps[64 * POOL_ROW_F];
    __shared__ float  sc1[64], sh1[64], b2s[64];
    __shared__ int    bgid[64];

    int tid = threadIdx.x;
    int node0 = blockIdx.x * 64;
    int warp = tid >> 5, lane = tid & 31;

    for (int idx = tid; idx < 64 * 64; idx += 256) {
        int krow = idx >> 6, ncol = idx & 63;
        W1s[krow * SMEM_ROW_H + ncol] = __float2half(W1[krow * 64 + ncol]);
        W2s[krow * SMEM_ROW_H + ncol] = __float2half(W2[krow * 64 + ncol]);
    }
    if (tid < 64) {
        float bn_scale = gam[tid] * rsqrtf(var[tid] + BN_EPS);
        sc1[tid] = bn_scale;
        sh1[tid] = fmaf(b1[tid] - mu[tid], bn_scale, bet[tid]);
        b2s[tid] = b2[tid];
        int node = node0 + tid;
        bgid[tid] = batch[(node < NN) ? node : (NN - 1)];
    }

    // gather phase: fp16 rows (32 half2/row), one half2 per lane; fp32 accumulate
    const __half2* xin2 = (const __half2*)xin;
#pragma unroll 1
    for (int i = 0; i < 8; i++) {
        int r = warp * 8 + i;
        int node = node0 + r;
        float2 acc = make_float2(0.f, 0.f);
        if (node < NN) {
            acc = __half22float2(xin2[node * 32 + lane]);
            int s = g_rowptr[node], e = g_rowptr[node + 1];
            for (int base = s; base < e; base += 32) {
                int cnt = min(32, e - base);
                int cidx = (lane < cnt) ? g_col[base + lane] : 0;
                int t = 0;
                for (; t + 4 <= cnt; t += 4) {
                    int j0 = __shfl_sync(0xffffffffu, cidx, t);
                    int j1 = __shfl_sync(0xffffffffu, cidx, t + 1);
                    int j2 = __shfl_sync(0xffffffffu, cidx, t + 2);
                    int j3 = __shfl_sync(0xffffffffu, cidx, t + 3);
                    float2 v0 = __half22float2(xin2[j0 * 32 + lane]);
                    float2 v1 = __half22float2(xin2[j1 * 32 + lane]);
                    float2 v2 = __half22float2(xin2[j2 * 32 + lane]);
                    float2 v3 = __half22float2(xin2[j3 * 32 + lane]);
                    acc.x += (v0.x + v1.x) + (v2.x + v3.x);
                    acc.y += (v0.y + v1.y) + (v2.y + v3.y);
                }
                for (; t < cnt; t++) {
                    int j = __shfl_sync(0xffffffffu, cidx, t);
                    float2 vv = __half22float2(xin2[j * 32 + lane]);
                    acc.x += vv.x; acc.y += vv.y;
                }
            }
        }
        *(__half2*)&As[r * SMEM_ROW_H + lane * 2] = __floats2half2_rn(acc.x, acc.y);
    }
    __syncthreads();

    int mma_row = warp & 3;
    int mma_col = (warp >> 2) * 32;
    unsigned int base_as = (unsigned int)__cvta_generic_to_shared(As);
    unsigned int base_w1 = (unsigned int)__cvta_generic_to_shared(W1s);
    unsigned int base_w2 = (unsigned int)__cvta_generic_to_shared(W2s);
    int off_a = (mma_row * 16 + (lane & 15)) * SMEM_ROW_H + ((lane >> 4) << 3);
    int off_w = (lane & 15) * SMEM_ROW_H + mma_col + ((lane >> 4) << 3);

    // GEMM1: T = A @ W1 (4 k-chunks)
    float acc1[4][4];
#pragma unroll
    for (int i = 0; i < 4; i++)
#pragma unroll
        for (int j = 0; j < 4; j++) acc1[i][j] = 0.f;
#pragma unroll
    for (int kc = 0; kc < 4; kc++) {
        unsigned int frag_a[4];
        unsigned int frag_b_lo[4];
        unsigned int frag_b_hi[4];
        gin_ldsm_a(frag_a, base_as + (unsigned int)((off_a + kc * 16) * 2));
        gin_ldsm_bt(frag_b_lo, base_w1 + (unsigned int)((off_w + kc * 16 * SMEM_ROW_H) * 2));
        gin_ldsm_bt(frag_b_hi, base_w1 + (unsigned int)((off_w + kc * 16 * SMEM_ROW_H + 16) * 2));
        gin_mma(acc1[0], frag_a, frag_b_lo[0], frag_b_lo[1]);
        gin_mma(acc1[1], frag_a, frag_b_lo[2], frag_b_lo[3]);
        gin_mma(acc1[2], frag_a, frag_b_hi[0], frag_b_hi[1]);
        gin_mma(acc1[3], frag_a, frag_b_hi[2], frag_b_hi[3]);
    }
    __syncthreads();

    // epilogue1: BN+ReLU -> As (fp16)
    {
        int row_out = mma_row * 16 + (lane >> 2);
#pragma unroll
        for (int j = 0; j < 4; j++) {
            int c = mma_col + j * 8 + ((lane & 3) << 1);
            float o00 = fmaxf(fmaf(acc1[j][0], sc1[c],     sh1[c]),     0.f);
            float o01 = fmaxf(fmaf(acc1[j][1], sc1[c + 1], sh1[c + 1]), 0.f);
            float o10 = fmaxf(fmaf(acc1[j][2], sc1[c],     sh1[c]),     0.f);
            float o11 = fmaxf(fmaf(acc1[j][3], sc1[c + 1], sh1[c + 1]), 0.f);
            *(__half2*)&As[row_out * SMEM_ROW_H + c]       = __floats2half2_rn(o00, o01);
            *(__half2*)&As[(row_out + 8) * SMEM_ROW_H + c] = __floats2half2_rn(o10, o11);
        }
    }
    __syncthreads();

    // GEMM2: O = T @ W2
    float acc2[4][4];
#pragma unroll
    for (int i = 0; i < 4; i++)
#pragma unroll
        for (int j = 0; j < 4; j++) acc2[i][j] = 0.f;
#pragma unroll
    for (int kc = 0; kc < 4; kc++) {
        unsigned int frag_a[4];
        unsigned int frag_b_lo[4];
        unsigned int frag_b_hi[4];
        gin_ldsm_a(frag_a, base_as + (unsigned int)((off_a + kc * 16) * 2));
        gin_ldsm_bt(frag_b_lo, base_w2 + (unsigned int)((off_w + kc * 16 * SMEM_ROW_H) * 2));
        gin_ldsm_bt(frag_b_hi, base_w2 + (unsigned int)((off_w + kc * 16 * SMEM_ROW_H + 16) * 2));
        gin_mma(acc2[0], frag_a, frag_b_lo[0], frag_b_lo[1]);
        gin_mma(acc2[1], frag_a, frag_b_lo[2], frag_b_lo[3]);
        gin_mma(acc2[2], frag_a, frag_b_hi[0], frag_b_hi[1]);
        gin_mma(acc2[3], frag_a, frag_b_hi[2], frag_b_hi[3]);
    }

    // epilogue2: +b2, ReLU -> hout (fp16) + Ps (f32 staging)
    {
        int row_half = mma_row * 16 + (lane >> 2);
#pragma unroll
        for (int hb = 0; hb < 2; hb++) {
            int r = row_half + hb * 8;
            int node = node0 + r;
            bool valid = (node < NN);
#pragma unroll
            for (int j = 0; j < 4; j++) {
                int c = mma_col + j * 8 + ((lane & 3) << 1);
                float o0 = valid ? fmaxf(acc2[j][hb * 2 + 0] + b2s[c],     0.f) : 0.f;
                float o1 = valid ? fmaxf(acc2[j][hb * 2 + 1] + b2s[c + 1], 0.f) : 0.f;
                if (valid)
                    *(__half2*)&hout[(size_t)node * 64 + c] = __floats2half2_rn(o0, o1);
                *(float2*)&Ps[r * POOL_ROW_F + c] = make_float2(o0, o1);
            }
        }
    }
    __syncthreads();

    // pooled readout
    {
        int col = tid & 63;
        int seg = tid >> 6;
        int rbeg = seg * 16;
        int cur = bgid[rbeg];
        float run = 0.f;
#pragma unroll
        for (int r = rbeg; r < rbeg + 16; r++) {
            int gid = bgid[r];
            if (gid != cur) {
                atomicAdd(&g_pool[cur * POOLW + pool_off + col], run);
                run = 0.f; cur = gid;
            }
            run += Ps[r * POOL_ROW_F + col];
        }
        atomicAdd(&g_pool[cur * POOLW + pool_off + col], run);
    }
}

// ---------------- head: fc1(192->192)+ReLU, fc2(192->2), log_softmax ----------------
__global__ void head_kernel(const float* __restrict__ fc1W, const float* __restrict__ fc1b,
                            const float* __restrict__ fc2W, const float* __restrict__ fc2b,
                            float* __restrict__ out) {
    __shared__ float h[POOLW];
    __shared__ float h2[POOLW];
    __shared__ float r0s[6], r1s[6];
    int g = blockIdx.x, t = threadIdx.x;
    h[t] = g_pool[g * POOLW + t];
    __syncthreads();
    float acc = fc1b[t];
#pragma unroll 8
    for (int k = 0; k < POOLW; k++) acc = fmaf(h[k], fc1W[k * POOLW + t], acc);
    h2[t] = fmaxf(acc, 0.f);
    __syncthreads();
    float p0 = h2[t] * fc2W[t * 2 + 0];
    float p1 = h2[t] * fc2W[t * 2 + 1];
#pragma unroll
    for (int o = 16; o > 0; o >>= 1) {
        p0 += __shfl_down_sync(0xffffffffu, p0, o);
        p1 += __shfl_down_sync(0xffffffffu, p1, o);
    }
    if ((t & 31) == 0) { r0s[t >> 5] = p0; r1s[t >> 5] = p1; }
    __syncthreads();
    if (t == 0) {
        float z0 = fc2b[0], z1 = fc2b[1];
#pragma unroll
        for (int w = 0; w < 6; w++) { z0 += r0s[w]; z1 += r1s[w]; }
        float mx = fmaxf(z0, z1);
        float lse = mx + logf(expf(z0 - mx) + expf(z1 - mx));
        out[g * 2 + 0] = z0 - lse;
        out[g * 2 + 1] = z1 - lse;
    }
}

// ---------------- launch ----------------
extern "C" void kernel_launch(void* const* d_in, const int* in_sizes, int n_in,
                              void* d_out, int out_size) {
    const float* x     = (const float*)d_in[0];
    const int*   src   = (const int*)d_in[1];
    const int*   dst   = (const int*)d_in[2];
    const int*   batch = (const int*)d_in[3];

    const float* c1p[8]; for (int i = 0; i < 8; i++) c1p[i] = (const float*)d_in[4 + i];
    const float* c2p[8]; for (int i = 0; i < 8; i++) c2p[i] = (const float*)d_in[12 + i];
    const float* c3p[8]; for (int i = 0; i < 8; i++) c3p[i] = (const float*)d_in[20 + i];
    const float* fc1W = (const float*)d_in[28];
    const float* fc1b = (const float*)d_in[29];
    const float* fc2W = (const float*)d_in[30];
    const float* fc2b = (const float*)d_in[31];
    float* out = (float*)d_out;

    __half *hA_p, *hB_p;
    cudaGetSymbolAddress((void**)&hA_p, g_hA);
    cudaGetSymbolAddress((void**)&hB_p, g_hB);

    const int TPB = 256;
    int blkN = (NN + TPB - 1) / TPB;                 // 391
    int blkE4 = (EE / 4 + TPB - 1) / TPB;            // 3125 (4 edges/thread)
    int blkM = (NN + 63) / 64;                       // 1563

    // CSR build
    init_zero_kernel<<<blkN, TPB>>>();
    hist_kernel<<<blkE4, TPB>>>(dst);
    scan_kernel<<<1, 1024>>>();
    scatter_kernel<<<blkE4, TPB>>>(src, dst);

    // fused GIN layers (gather + tensor-core MLP + pooling)
    gin_layer_first_kernel<<<blkM, TPB>>>(x, c1p[0], c1p[1], c1p[2], c1p[3], c1p[4],
                                          c1p[5], c1p[6], c1p[7], batch, hA_p, 0);
    gin_layer_hidden_kernel<<<blkM, TPB>>>(hA_p, c2p[0], c2p[1], c2p[2], c2p[3], c2p[4],
                                           c2p[5], c2p[6], c2p[7], batch, hB_p, 64);
    gin_layer_hidden_kernel<<<blkM, TPB>>>(hB_p, c3p[0], c3p[1], c3p[2], c3p[3], c3p[4],
                                           c3p[5], c3p[6], c3p[7], batch, hA_p, 128);

    // readout head
    head_kernel<<<GG, POOLW>>>(fc1W, fc1b, fc2W, fc2b, out);
}

// round 9
// speedup vs baseline: 1.7218x; 1.2119x over previous
#include <cuda_runtime.h>
#include <cuda_fp16.h>
#include <stdint.h>
#include <math.h>

#define NN 100000
#define EE 3200000
#define FF 13
#define HH 64
#define GG 512
#define POOLW 192
#define BN_EPS 1e-5f
#define NBLK 391   /* ceil(NN/256) */

// ---------------- scratch (device globals: allocation-free) ----------------
__device__ int    g_deg[NN];
__device__ int    g_rowptr[NN + 1];
__device__ int    g_cursor[NN];
__device__ int    g_col[EE];
__device__ int    g_bsum[512];
__device__ __half g_hA[NN * 64];
__device__ __half g_hB[NN * 64];
__device__ float  g_pool[GG * POOLW];

// ---------------- PTX helpers ----------------
__device__ __forceinline__ void gin_ldsm_a(unsigned int* frag_out4, unsigned int smem_addr_u32) {
    asm volatile("ldmatrix.sync.aligned.m8n8.x4.shared.b16 {%0,%1,%2,%3}, [%4];"
                 : "=r"(frag_out4[0]), "=r"(frag_out4[1]),
                   "=r"(frag_out4[2]), "=r"(frag_out4[3])
                 : "r"(smem_addr_u32));
}

__device__ __forceinline__ void gin_ldsm_bt(unsigned int* frag_out4, unsigned int smem_addr_u32) {
    asm volatile("ldmatrix.sync.aligned.m8n8.x4.trans.shared.b16 {%0,%1,%2,%3}, [%4];"
                 : "=r"(frag_out4[0]), "=r"(frag_out4[1]),
                   "=r"(frag_out4[2]), "=r"(frag_out4[3])
                 : "r"(smem_addr_u32));
}

__device__ __forceinline__ void gin_mma(float* acc_inout4, const unsigned int* frag_a4,
                                        unsigned int frag_b_first, unsigned int frag_b_second) {
    asm volatile(
        "mma.sync.aligned.m16n8k16.row.col.f32.f16.f16.f32 "
        "{%0,%1,%2,%3}, {%4,%5,%6,%7}, {%8,%9}, {%0,%1,%2,%3};"
        : "+f"(acc_inout4[0]), "+f"(acc_inout4[1]),
          "+f"(acc_inout4[2]), "+f"(acc_inout4[3])
        : "r"(frag_a4[0]), "r"(frag_a4[1]), "r"(frag_a4[2]), "r"(frag_a4[3]),
          "r"(frag_b_first), "r"(frag_b_second));
}

// ---------------- CSR build ----------------
__global__ void init_zero_kernel() {
    int i = blockIdx.x * blockDim.x + threadIdx.x;
    if (i < NN) g_deg[i] = 0;
    if (i < GG * POOLW) g_pool[i] = 0.f;
}

__global__ void hist_kernel(const int* __restrict__ dst) {
    int i = (blockIdx.x * blockDim.x + threadIdx.x) * 4;
    if (i < EE) {  // EE % 4 == 0
        int4 dstv = *(const int4*)&dst[i];
        atomicAdd(&g_deg[dstv.x], 1);
        atomicAdd(&g_deg[dstv.y], 1);
        atomicAdd(&g_deg[dstv.z], 1);
        atomicAdd(&g_deg[dstv.w], 1);
    }
}

// Hierarchical scan, stage 1: per-block (256-wide) exclusive scan + block sums
__global__ void scan_block_kernel() {
    __shared__ int wsum[8];
    int tid = threadIdx.x;
    int i = blockIdx.x * 256 + tid;
    int v = (i < NN) ? g_deg[i] : 0;
    int x = v;
#pragma unroll
    for (int o = 1; o < 32; o <<= 1) {
        int y = __shfl_up_sync(0xffffffffu, x, o);
        if ((tid & 31) >= o) x += y;
    }
    if ((tid & 31) == 31) wsum[tid >> 5] = x;
    __syncthreads();
    if (tid == 0) {
        int run = 0;
#pragma unroll
        for (int w = 0; w < 8; w++) { int tmpv = wsum[w]; wsum[w] = run; run += tmpv; }
        g_bsum[blockIdx.x] = run;
    }
    __syncthreads();
    if (i < NN) g_rowptr[i] = x - v + wsum[tid >> 5];   // block-local exclusive
}

// Stage 2: single-block exclusive scan over the 391 block sums (in place)
__global__ void scan_bsum_kernel() {
    __shared__ int svals[512];
    __shared__ int wsum[16];
    int tid = threadIdx.x;   // 512 threads
    int v = (tid < NBLK) ? g_bsum[tid] : 0;
    svals[tid] = v;
    __syncthreads();
    int x = v;
#pragma unroll
    for (int o = 1; o < 32; o <<= 1) {
        int y = __shfl_up_sync(0xffffffffu, x, o);
        if ((tid & 31) >= o) x += y;
    }
    if ((tid & 31) == 31) wsum[tid >> 5] = x;
    __syncthreads();
    if (tid == 0) {
        int run = 0;
#pragma unroll
        for (int w = 0; w < 16; w++) { int tmpv = wsum[w]; wsum[w] = run; run += tmpv; }
    }
    __syncthreads();
    if (tid < NBLK) g_bsum[tid] = x - v + wsum[tid >> 5];
}

// Stage 3: add block offsets, init cursor, set rowptr[NN]
__global__ void scan_add_kernel() {
    int tid = threadIdx.x;
    int i = blockIdx.x * 256 + tid;
    if (i < NN) {
        int val = g_rowptr[i] + g_bsum[blockIdx.x];
        g_rowptr[i] = val;
        g_cursor[i] = val;
    }
    if (i == 0) g_rowptr[NN] = EE;
}

__global__ void scatter_kernel(const int* __restrict__ src, const int* __restrict__ dst) {
    int i = (blockIdx.x * blockDim.x + threadIdx.x) * 4;
    if (i < EE) {
        int4 dstv = *(const int4*)&dst[i];
        int4 srcv = *(const int4*)&src[i];
        int p0 = atomicAdd(&g_cursor[dstv.x], 1);
        int p1 = atomicAdd(&g_cursor[dstv.y], 1);
        int p2 = atomicAdd(&g_cursor[dstv.z], 1);
        int p3 = atomicAdd(&g_cursor[dstv.w], 1);
        g_col[p0] = srcv.x;
        g_col[p1] = srcv.y;
        g_col[p2] = srcv.z;
        g_col[p3] = srcv.w;
    }
}

// smem layout constants for the layer kernels
#define SMEM_ROW_H 72   /* half elements per row (144B): ldmatrix conflict-free */
#define POOL_ROW_F 68   /* float elements per row of pool staging */

// ---------------- layer 1: FIN=13 fp32 input, tensor-core MLP + pooling ----------------
__global__ void __launch_bounds__(256)
gin_layer_first_kernel(const float* __restrict__ xin,
                       const float* __restrict__ W1, const float* __restrict__ b1,
                       const float* __restrict__ gam, const float* __restrict__ bet,
                       const float* __restrict__ mu, const float* __restrict__ var,
                       const float* __restrict__ W2, const float* __restrict__ b2,
                       const int* __restrict__ batch,
                       __half* __restrict__ hout, int pool_off) {
    __shared__ __half As[64 * SMEM_ROW_H];
    __shared__ __half W1s[64 * SMEM_ROW_H];
    __shared__ __half W2s[64 * SMEM_ROW_H];
    __shared__ float  Ps[64 * POOL_ROW_F];
    __shared__ float  sc1[64], sh1[64], b2s[64];
    __shared__ int    bgid[64];

    int tid = threadIdx.x;
    int node0 = blockIdx.x * 64;
    int warp = tid >> 5, lane = tid & 31;

    for (int idx = tid; idx < 16 * 64; idx += 256) {
        int krow = idx >> 6, ncol = idx & 63;
        W1s[krow * SMEM_ROW_H + ncol] = __float2half((krow < FF) ? W1[krow * 64 + ncol] : 0.f);
    }
    for (int idx = tid; idx < 64 * 64; idx += 256) {
        int krow = idx >> 6, ncol = idx & 63;
        W2s[krow * SMEM_ROW_H + ncol] = __float2half(W2[krow * 64 + ncol]);
    }
    if (tid < 64) {
        float bn_scale = gam[tid] * rsqrtf(var[tid] + BN_EPS);
        sc1[tid] = bn_scale;
        sh1[tid] = fmaf(b1[tid] - mu[tid], bn_scale, bet[tid]);
        b2s[tid] = b2[tid];
        int node = node0 + tid;
        bgid[tid] = batch[(node < NN) ? node : (NN - 1)];
    }

    // gather: 8-wide edge unroll + next-chunk index prefetch
#pragma unroll 1
    for (int i = 0; i < 8; i++) {
        int r = warp * 8 + i;
        int node = node0 + r;
        float acc = 0.f;
        if (node < NN && lane < FF) acc = xin[node * FF + lane];
        if (node < NN) {
            int s = g_rowptr[node], e = g_rowptr[node + 1];
            int cidx = (s + lane < e) ? g_col[s + lane] : 0;
#pragma unroll 1
            for (int cb = s; cb < e; cb += 32) {
                int cnt = min(32, e - cb);
                int cidx_next = (cb + 32 + lane < e) ? g_col[cb + 32 + lane] : 0;
                int t = 0;
                for (; t + 8 <= cnt; t += 8) {
                    int jj[8];
#pragma unroll
                    for (int q = 0; q < 8; q++) jj[q] = __shfl_sync(0xffffffffu, cidx, t + q);
                    if (lane < FF) {
                        float vv[8];
#pragma unroll
                        for (int q = 0; q < 8; q++) vv[q] = xin[jj[q] * FF + lane];
                        acc += ((vv[0] + vv[1]) + (vv[2] + vv[3])) +
                               ((vv[4] + vv[5]) + (vv[6] + vv[7]));
                    }
                }
                for (; t < cnt; t++) {
                    int j = __shfl_sync(0xffffffffu, cidx, t);
                    if (lane < FF) acc += xin[j * FF + lane];
                }
                cidx = cidx_next;
            }
        }
        if (lane < 16) As[r * SMEM_ROW_H + lane] = __float2half((lane < FF) ? acc : 0.f);
    }
    __syncthreads();

    int mma_row = warp & 3;
    int mma_col = (warp >> 2) * 32;
    unsigned int base_as = (unsigned int)__cvta_generic_to_shared(As);
    unsigned int base_w1 = (unsigned int)__cvta_generic_to_shared(W1s);
    unsigned int base_w2 = (unsigned int)__cvta_generic_to_shared(W2s);
    int off_a = (mma_row * 16 + (lane & 15)) * SMEM_ROW_H + ((lane >> 4) << 3);
    int off_w = (lane & 15) * SMEM_ROW_H + mma_col + ((lane >> 4) << 3);

    // GEMM1 (KPAD=16 -> single k-chunk)
    float acc1[4][4];
#pragma unroll
    for (int i = 0; i < 4; i++)
#pragma unroll
        for (int j = 0; j < 4; j++) acc1[i][j] = 0.f;
    {
        unsigned int frag_a[4];
        unsigned int frag_b_lo[4];
        unsigned int frag_b_hi[4];
        gin_ldsm_a(frag_a, base_as + (unsigned int)(off_a * 2));
        gin_ldsm_bt(frag_b_lo, base_w1 + (unsigned int)(off_w * 2));
        gin_ldsm_bt(frag_b_hi, base_w1 + (unsigned int)((off_w + 16) * 2));
        gin_mma(acc1[0], frag_a, frag_b_lo[0], frag_b_lo[1]);
        gin_mma(acc1[1], frag_a, frag_b_lo[2], frag_b_lo[3]);
        gin_mma(acc1[2], frag_a, frag_b_hi[0], frag_b_hi[1]);
        gin_mma(acc1[3], frag_a, frag_b_hi[2], frag_b_hi[3]);
    }
    __syncthreads();

    // epilogue1: BN+ReLU -> As (fp16)
    {
        int row_out = mma_row * 16 + (lane >> 2);
#pragma unroll
        for (int j = 0; j < 4; j++) {
            int c = mma_col + j * 8 + ((lane & 3) << 1);
            float o00 = fmaxf(fmaf(acc1[j][0], sc1[c],     sh1[c]),     0.f);
            float o01 = fmaxf(fmaf(acc1[j][1], sc1[c + 1], sh1[c + 1]), 0.f);
            float o10 = fmaxf(fmaf(acc1[j][2], sc1[c],     sh1[c]),     0.f);
            float o11 = fmaxf(fmaf(acc1[j][3], sc1[c + 1], sh1[c + 1]), 0.f);
            *(__half2*)&As[row_out * SMEM_ROW_H + c]       = __floats2half2_rn(o00, o01);
            *(__half2*)&As[(row_out + 8) * SMEM_ROW_H + c] = __floats2half2_rn(o10, o11);
        }
    }
    __syncthreads();

    // GEMM2
    float acc2[4][4];
#pragma unroll
    for (int i = 0; i < 4; i++)
#pragma unroll
        for (int j = 0; j < 4; j++) acc2[i][j] = 0.f;
#pragma unroll
    for (int kc = 0; kc < 4; kc++) {
        unsigned int frag_a[4];
        unsigned int frag_b_lo[4];
        unsigned int frag_b_hi[4];
        gin_ldsm_a(frag_a, base_as + (unsigned int)((off_a + kc * 16) * 2));
        gin_ldsm_bt(frag_b_lo, base_w2 + (unsigned int)((off_w + kc * 16 * SMEM_ROW_H) * 2));
        gin_ldsm_bt(frag_b_hi, base_w2 + (unsigned int)((off_w + kc * 16 * SMEM_ROW_H + 16) * 2));
        gin_mma(acc2[0], frag_a, frag_b_lo[0], frag_b_lo[1]);
        gin_mma(acc2[1], frag_a, frag_b_lo[2], frag_b_lo[3]);
        gin_mma(acc2[2], frag_a, frag_b_hi[0], frag_b_hi[1]);
        gin_mma(acc2[3], frag_a, frag_b_hi[2], frag_b_hi[3]);
    }

    // epilogue2
    {
        int row_half = mma_row * 16 + (lane >> 2);
#pragma unroll
        for (int hb = 0; hb < 2; hb++) {
            int r = row_half + hb * 8;
            int node = node0 + r;
            bool valid = (node < NN);
#pragma unroll
            for (int j = 0; j < 4; j++) {
                int c = mma_col + j * 8 + ((lane & 3) << 1);
                float o0 = valid ? fmaxf(acc2[j][hb * 2 + 0] + b2s[c],     0.f) : 0.f;
                float o1 = valid ? fmaxf(acc2[j][hb * 2 + 1] + b2s[c + 1], 0.f) : 0.f;
                if (valid)
                    *(__half2*)&hout[(size_t)node * 64 + c] = __floats2half2_rn(o0, o1);
                *(float2*)&Ps[r * POOL_ROW_F + c] = make_float2(o0, o1);
            }
        }
    }
    __syncthreads();

    // pooled readout
    {
        int col = tid & 63;
        int seg = tid >> 6;
        int rbeg = seg * 16;
        int cur = bgid[rbeg];
        float run = 0.f;
#pragma unroll
        for (int r = rbeg; r < rbeg + 16; r++) {
            int gid = bgid[r];
            if (gid != cur) {
                atomicAdd(&g_pool[cur * POOLW + pool_off + col], run);
                run = 0.f; cur = gid;
            }
            run += Ps[r * POOL_ROW_F + col];
        }
        atomicAdd(&g_pool[cur * POOLW + pool_off + col], run);
    }
}

// ---------------- layers 2,3: FIN=64 fp16 input, tensor-core MLP + pooling ----------------
__global__ void __launch_bounds__(256)
gin_layer_hidden_kernel(const __half* __restrict__ xin,
                        const float* __restrict__ W1, const float* __restrict__ b1,
                        const float* __restrict__ gam, const float* __restrict__ bet,
                        const float* __restrict__ mu, const float* __restrict__ var,
                        const float* __restrict__ W2, const float* __restrict__ b2,
                        const int* __restrict__ batch,
                        __half* __restrict__ hout, int pool_off) {
    __shared__ __half As[64 * SMEM_ROW_H];
    __shared__ __half W1s[64 * SMEM_ROW_H];
    __shared__ __half W2s[64 * SMEM_ROW_H];
    __shared__ float  Ps[64 * POOL_ROW_F];
    __shared__ float  sc1[64], sh1[64], b2s[64];
    __shared__ int    bgid[64];

    int tid = threadIdx.x;
    int node0 = blockIdx.x * 64;
    int warp = tid >> 5, lane = tid & 31;

    for (int idx = tid; idx < 64 * 64; idx += 256) {
        int krow = idx >> 6, ncol = idx & 63;
        W1s[krow * SMEM_ROW_H + ncol] = __float2half(W1[krow * 64 + ncol]);
        W2s[krow * SMEM_ROW_H + ncol] = __float2half(W2[krow * 64 + ncol]);
    }
    if (tid < 64) {
        float bn_scale = gam[tid] * rsqrtf(var[tid] + BN_EPS);
        sc1[tid] = bn_scale;
        sh1[tid] = fmaf(b1[tid] - mu[tid], bn_scale, bet[tid]);
        b2s[tid] = b2[tid];
        int node = node0 + tid;
        bgid[tid] = batch[(node < NN) ? node : (NN - 1)];
    }

    // gather: fp16 rows (32 half2/row); 8-wide edge unroll + index prefetch
    const __half2* xin2 = (const __half2*)xin;
#pragma unroll 1
    for (int i = 0; i < 8; i++) {
        int r = warp * 8 + i;
        int node = node0 + r;
        float2 acc = make_float2(0.f, 0.f);
        if (node < NN) {
            acc = __half22float2(xin2[node * 32 + lane]);
            int s = g_rowptr[node], e = g_rowptr[node + 1];
            int cidx = (s + lane < e) ? g_col[s + lane] : 0;
#pragma unroll 1
            for (int cb = s; cb < e; cb += 32) {
                int cnt = min(32, e - cb);
                int cidx_next = (cb + 32 + lane < e) ? g_col[cb + 32 + lane] : 0;
                int t = 0;
                for (; t + 8 <= cnt; t += 8) {
                    int jj[8];
#pragma unroll
                    for (int q = 0; q < 8; q++) jj[q] = __shfl_sync(0xffffffffu, cidx, t + q);
                    float2 vv[8];
#pragma unroll
                    for (int q = 0; q < 8; q++) vv[q] = __half22float2(xin2[jj[q] * 32 + lane]);
                    acc.x += ((vv[0].x + vv[1].x) + (vv[2].x + vv[3].x)) +
                             ((vv[4].x + vv[5].x) + (vv[6].x + vv[7].x));
                    acc.y += ((vv[0].y + vv[1].y) + (vv[2].y + vv[3].y)) +
                             ((vv[4].y + vv[5].y) + (vv[6].y + vv[7].y));
                }
                for (; t < cnt; t++) {
                    int j = __shfl_sync(0xffffffffu, cidx, t);
                    float2 vv = __half22float2(xin2[j * 32 + lane]);
                    acc.x += vv.x; acc.y += vv.y;
                }
                cidx = cidx_next;
            }
        }
        *(__half2*)&As[r * SMEM_ROW_H + lane * 2] = __floats2half2_rn(acc.x, acc.y);
    }
    __syncthreads();

    int mma_row = warp & 3;
    int mma_col = (warp >> 2) * 32;
    unsigned int base_as = (unsigned int)__cvta_generic_to_shared(As);
    unsigned int base_w1 = (unsigned int)__cvta_generic_to_shared(W1s);
    unsigned int base_w2 = (unsigned int)__cvta_generic_to_shared(W2s);
    int off_a = (mma_row * 16 + (lane & 15)) * SMEM_ROW_H + ((lane >> 4) << 3);
    int off_w = (lane & 15) * SMEM_ROW_H + mma_col + ((lane >> 4) << 3);

    // GEMM1
    float acc1[4][4];
#pragma unroll
    for (int i = 0; i < 4; i++)
#pragma unroll
        for (int j = 0; j < 4; j++) acc1[i][j] = 0.f;
#pragma unroll
    for (int kc = 0; kc < 4; kc++) {
        unsigned int frag_a[4];
        unsigned int frag_b_lo[4];
        unsigned int frag_b_hi[4];
        gin_ldsm_a(frag_a, base_as + (unsigned int)((off_a + kc * 16) * 2));
        gin_ldsm_bt(frag_b_lo, base_w1 + (unsigned int)((off_w + kc * 16 * SMEM_ROW_H) * 2));
        gin_ldsm_bt(frag_b_hi, base_w1 + (unsigned int)((off_w + kc * 16 * SMEM_ROW_H + 16) * 2));
        gin_mma(acc1[0], frag_a, frag_b_lo[0], frag_b_lo[1]);
        gin_mma(acc1[1], frag_a, frag_b_lo[2], frag_b_lo[3]);
        gin_mma(acc1[2], frag_a, frag_b_hi[0], frag_b_hi[1]);
        gin_mma(acc1[3], frag_a, frag_b_hi[2], frag_b_hi[3]);
    }
    __syncthreads();

    // epilogue1: BN+ReLU -> As (fp16)
    {
        int row_out = mma_row * 16 + (lane >> 2);
#pragma unroll
        for (int j = 0; j < 4; j++) {
            int c = mma_col + j * 8 + ((lane & 3) << 1);
            float o00 = fmaxf(fmaf(acc1[j][0], sc1[c],     sh1[c]),     0.f);
            float o01 = fmaxf(fmaf(acc1[j][1], sc1[c + 1], sh1[c + 1]), 0.f);
            float o10 = fmaxf(fmaf(acc1[j][2], sc1[c],     sh1[c]),     0.f);
            float o11 = fmaxf(fmaf(acc1[j][3], sc1[c + 1], sh1[c + 1]), 0.f);
            *(__half2*)&As[row_out * SMEM_ROW_H + c]       = __floats2half2_rn(o00, o01);
            *(__half2*)&As[(row_out + 8) * SMEM_ROW_H + c] = __floats2half2_rn(o10, o11);
        }
    }
    __syncthreads();

    // GEMM2
    float acc2[4][4];
#pragma unroll
    for (int i = 0; i < 4; i++)
#pragma unroll
        for (int j = 0; j < 4; j++) acc2[i][j] = 0.f;
#pragma unroll
    for (int kc = 0; kc < 4; kc++) {
        unsigned int frag_a[4];
        unsigned int frag_b_lo[4];
        unsigned int frag_b_hi[4];
        gin_ldsm_a(frag_a, base_as + (unsigned int)((off_a + kc * 16) * 2));
        gin_ldsm_bt(frag_b_lo, base_w2 + (unsigned int)((off_w + kc * 16 * SMEM_ROW_H) * 2));
        gin_ldsm_bt(frag_b_hi, base_w2 + (unsigned int)((off_w + kc * 16 * SMEM_ROW_H + 16) * 2));
        gin_mma(acc2[0], frag_a, frag_b_lo[0], frag_b_lo[1]);
        gin_mma(acc2[1], frag_a, frag_b_lo[2], frag_b_lo[3]);
        gin_mma(acc2[2], frag_a, frag_b_hi[0], frag_b_hi[1]);
        gin_mma(acc2[3], frag_a, frag_b_hi[2], frag_b_hi[3]);
    }

    // epilogue2
    {
        int row_half = mma_row * 16 + (lane >> 2);
#pragma unroll
        for (int hb = 0; hb < 2; hb++) {
            int r = row_half + hb * 8;
            int node = node0 + r;
            bool valid = (node < NN);
#pragma unroll
            for (int j = 0; j < 4; j++) {
                int c = mma_col + j * 8 + ((lane & 3) << 1);
                float o0 = valid ? fmaxf(acc2[j][hb * 2 + 0] + b2s[c],     0.f) : 0.f;
                float o1 = valid ? fmaxf(acc2[j][hb * 2 + 1] + b2s[c + 1], 0.f) : 0.f;
                if (valid)
                    *(__half2*)&hout[(size_t)node * 64 + c] = __floats2half2_rn(o0, o1);
                *(float2*)&Ps[r * POOL_ROW_F + c] = make_float2(o0, o1);
            }
        }
    }
    __syncthreads();

    // pooled readout
    {
        int col = tid & 63;
        int seg = tid >> 6;
        int rbeg = seg * 16;
        int cur = bgid[rbeg];
        float run = 0.f;
#pragma unroll
        for (int r = rbeg; r < rbeg + 16; r++) {
            int gid = bgid[r];
            if (gid != cur) {
                atomicAdd(&g_pool[cur * POOLW + pool_off + col], run);
                run = 0.f; cur = gid;
            }
            run += Ps[r * POOL_ROW_F + col];
        }
        atomicAdd(&g_pool[cur * POOLW + pool_off + col], run);
    }
}

// ---------------- head: fc1(192->192)+ReLU, fc2(192->2), log_softmax ----------------
__global__ void head_kernel(const float* __restrict__ fc1W, const float* __restrict__ fc1b,
                            const float* __restrict__ fc2W, const float* __restrict__ fc2b,
                            float* __restrict__ out) {
    __shared__ float h[POOLW];
    __shared__ float h2[POOLW];
    __shared__ float r0s[6], r1s[6];
    int g = blockIdx.x, t = threadIdx.x;
    h[t] = g_pool[g * POOLW + t];
    __syncthreads();
    float acc = fc1b[t];
#pragma unroll 8
    for (int k = 0; k < POOLW; k++) acc = fmaf(h[k], fc1W[k * POOLW + t], acc);
    h2[t] = fmaxf(acc, 0.f);
    __syncthreads();
    float p0 = h2[t] * fc2W[t * 2 + 0];
    float p1 = h2[t] * fc2W[t * 2 + 1];
#pragma unroll
    for (int o = 16; o > 0; o >>= 1) {
        p0 += __shfl_down_sync(0xffffffffu, p0, o);
        p1 += __shfl_down_sync(0xffffffffu, p1, o);
    }
    if ((t & 31) == 0) { r0s[t >> 5] = p0; r1s[t >> 5] = p1; }
    __syncthreads();
    if (t == 0) {
        float z0 = fc2b[0], z1 = fc2b[1];
#pragma unroll
        for (int w = 0; w < 6; w++) { z0 += r0s[w]; z1 += r1s[w]; }
        float mx = fmaxf(z0, z1);
        float lse = mx + logf(expf(z0 - mx) + expf(z1 - mx));
        out[g * 2 + 0] = z0 - lse;
        out[g * 2 + 1] = z1 - lse;
    }
}

// ---------------- launch ----------------
extern "C" void kernel_launch(void* const* d_in, const int* in_sizes, int n_in,
                              void* d_out, int out_size) {
    const float* x     = (const float*)d_in[0];
    const int*   src   = (const int*)d_in[1];
    const int*   dst   = (const int*)d_in[2];
    const int*   batch = (const int*)d_in[3];

    const float* c1p[8]; for (int i = 0; i < 8; i++) c1p[i] = (const float*)d_in[4 + i];
    const float* c2p[8]; for (int i = 0; i < 8; i++) c2p[i] = (const float*)d_in[12 + i];
    const float* c3p[8]; for (int i = 0; i < 8; i++) c3p[i] = (const float*)d_in[20 + i];
    const float* fc1W = (const float*)d_in[28];
    const float* fc1b = (const float*)d_in[29];
    const float* fc2W = (const float*)d_in[30];
    const float* fc2b = (const float*)d_in[31];
    float* out = (float*)d_out;

    __half *hA_p, *hB_p;
    cudaGetSymbolAddress((void**)&hA_p, g_hA);
    cudaGetSymbolAddress((void**)&hB_p, g_hB);

    const int TPB = 256;
    int blkN = (NN + TPB - 1) / TPB;                 // 391
    int blkE4 = (EE / 4 + TPB - 1) / TPB;            // 3125 (4 edges/thread)
    int blkM = (NN + 63) / 64;                       // 1563

    // CSR build (hierarchical scan: 3 tiny kernels instead of 98-iter monolith)
    init_zero_kernel<<<blkN, TPB>>>();
    hist_kernel<<<blkE4, TPB>>>(dst);
    scan_block_kernel<<<NBLK, 256>>>();
    scan_bsum_kernel<<<1, 512>>>();
    scan_add_kernel<<<NBLK, 256>>>();
    scatter_kernel<<<blkE4, TPB>>>(src, dst);

    // fused GIN layers (gather + tensor-core MLP + pooling)
    gin_layer_first_kernel<<<blkM, TPB>>>(x, c1p[0], c1p[1], c1p[2], c1p[3], c1p[4],
                                          c1p[5], c1p[6], c1p[7], batch, hA_p, 0);
    gin_layer_hidden_kernel<<<blkM, TPB>>>(hA_p, c2p[0], c2p[1], c2p[2], c2p[3], c2p[4],
                                           c2p[5], c2p[6], c2p[7], batch, hB_p, 64);
    gin_layer_hidden_kernel<<<blkM, TPB>>>(hB_p, c3p[0], c3p[1], c3p[2], c3p[3], c3p[4],
                                           c3p[5], c3p[6], c3p[7], batch, hA_p, 128);

    // readout head
    head_kernel<<<GG, POOLW>>>(fc1W, fc1b, fc2W, fc2b, out);
}